// round 8
// baseline (speedup 1.0000x reference)
#include <cuda_runtime.h>
#include <cuda_bf16.h>
#include <math.h>
#include <stdint.h>

#define M_TOK 16384
#define V_DIM 4096
#define C_DIM 128
#define K_NB2 128
#define N_OPS 8

// ------------------------- scratch (device globals) -------------------------
__device__ float g_rw[V_DIM * C_DIM];                  // read scores fp32
__device__ __nv_bfloat16 g_rwTh[C_DIM * V_DIM];        // read_w^T hi (C x V)
__device__ __nv_bfloat16 g_rwTl[C_DIM * V_DIM];
__device__ __nv_bfloat16 g_wwh[V_DIM * C_DIM];         // write_w hi (V x C)
__device__ __nv_bfloat16 g_wwl[V_DIM * C_DIM];
__device__ __nv_bfloat16 g_wTh[N_OPS * C_DIM * C_DIM]; // op W^T [op][n][k]
__device__ __nv_bfloat16 g_wTl[N_OPS * C_DIM * C_DIM];

// ------------------------- helpers -------------------------
__device__ __forceinline__ uint32_t smem_u32(const void* p) {
    uint32_t a;
    asm("{ .reg .u64 t; cvta.to.shared.u64 t, %1; cvt.u32.u64 %0, t; }" : "=r"(a) : "l"(p));
    return a;
}
#define CP16(saddr, gptr) \
    asm volatile("cp.async.cg.shared.global [%0], [%1], 16;" :: "r"(saddr), "l"(gptr) : "memory")
#define CP_COMMIT() asm volatile("cp.async.commit_group;" ::: "memory")
template <int N> __device__ __forceinline__ void cp_wait() {
    asm volatile("cp.async.wait_group %0;" :: "n"(N) : "memory");
}
__device__ __forceinline__ void ldsm4(uint32_t& r0, uint32_t& r1, uint32_t& r2, uint32_t& r3, uint32_t a) {
    asm volatile("ldmatrix.sync.aligned.m8n8.x4.shared.b16 {%0,%1,%2,%3}, [%4];"
        : "=r"(r0), "=r"(r1), "=r"(r2), "=r"(r3) : "r"(a));
}
__device__ __forceinline__ void mma_bf16(float c[4], const uint32_t a[4], const uint32_t b[2]) {
    asm volatile(
        "mma.sync.aligned.m16n8k16.row.col.f32.bf16.bf16.f32 "
        "{%0,%1,%2,%3},{%4,%5,%6,%7},{%8,%9},{%0,%1,%2,%3};"
        : "+f"(c[0]), "+f"(c[1]), "+f"(c[2]), "+f"(c[3])
        : "r"(a[0]), "r"(a[1]), "r"(a[2]), "r"(a[3]), "r"(b[0]), "r"(b[1]));
}
__device__ __forceinline__ void split2(float a, float b, uint32_t& hi, uint32_t& lo) {
    __nv_bfloat16 ha = __float2bfloat16(a), hb = __float2bfloat16(b);
    __nv_bfloat16 la = __float2bfloat16(a - __bfloat162float(ha));
    __nv_bfloat16 lb = __float2bfloat16(b - __bfloat162float(hb));
    hi = (uint32_t)__bfloat16_as_ushort(ha) | ((uint32_t)__bfloat16_as_ushort(hb) << 16);
    lo = (uint32_t)__bfloat16_as_ushort(la) | ((uint32_t)__bfloat16_as_ushort(lb) << 16);
}
__device__ __forceinline__ void split1(float a, uint16_t& h, uint16_t& l) {
    __nv_bfloat16 ha = __float2bfloat16(a);
    __nv_bfloat16 la = __float2bfloat16(a - __bfloat162float(ha));
    h = __bfloat16_as_ushort(ha);
    l = __bfloat16_as_ushort(la);
}

// ---------------------------------------------------------------------------
// Addressing GEMM: scores = basis(4096x128) @ coeff(128x128)^T
// z=0: rcoef -> g_rw fp32;  z=1: wcoef -> split to g_wwh/g_wwl
// ---------------------------------------------------------------------------
__global__ __launch_bounds__(256) void sgemm_addr(
    const float* __restrict__ A, const float* __restrict__ B0,
    const float* __restrict__ B1)
{
    __shared__ float As[16][128];
    __shared__ float Bs[16][128];
    const int tid = threadIdx.x;
    const int tc = tid % 16, tr = tid / 16;
    const int m0 = blockIdx.y * 128;
    const int path = blockIdx.z;
    const float* B = path ? B1 : B0;

    float acc[8][8];
#pragma unroll
    for (int i = 0; i < 8; i++)
#pragma unroll
        for (int j = 0; j < 8; j++) acc[i][j] = 0.0f;

    for (int k0 = 0; k0 < K_NB2; k0 += 16) {
#pragma unroll
        for (int i = 0; i < 2; i++) {
            int idx = tid + i * 256;
            int row = idx / 4, c4 = idx % 4;
            float4 va = *(const float4*)&A[(size_t)(m0 + row) * K_NB2 + k0 + c4 * 4];
            As[c4 * 4 + 0][row] = va.x; As[c4 * 4 + 1][row] = va.y;
            As[c4 * 4 + 2][row] = va.z; As[c4 * 4 + 3][row] = va.w;
            float4 vb = *(const float4*)&B[(size_t)row * K_NB2 + k0 + c4 * 4];
            Bs[c4 * 4 + 0][row] = vb.x; Bs[c4 * 4 + 1][row] = vb.y;
            Bs[c4 * 4 + 2][row] = vb.z; Bs[c4 * 4 + 3][row] = vb.w;
        }
        __syncthreads();
#pragma unroll
        for (int k = 0; k < 16; k++) {
            float ra[8], rb[8];
#pragma unroll
            for (int i = 0; i < 8; i++) ra[i] = As[k][tr * 8 + i];
#pragma unroll
            for (int j = 0; j < 8; j++) rb[j] = Bs[k][tc * 8 + j];
#pragma unroll
            for (int i = 0; i < 8; i++)
#pragma unroll
                for (int j = 0; j < 8; j++) acc[i][j] += ra[i] * rb[j];
        }
        __syncthreads();
    }
#pragma unroll
    for (int i = 0; i < 8; i++) {
        const size_t base = (size_t)(m0 + tr * 8 + i) * C_DIM + tc * 8;
        if (path == 0) {
#pragma unroll
            for (int j = 0; j < 8; j++) g_rw[base + j] = acc[i][j];
        } else {
#pragma unroll
            for (int j = 0; j < 8; j++) {
                uint16_t h, l;
                split1(acc[i][j], h, l);
                g_wwh[base + j] = __ushort_as_bfloat16(h);
                g_wwl[base + j] = __ushort_as_bfloat16(l);
            }
        }
    }
}

// ---------------------------------------------------------------------------
// Column softmax over V (axis 0); write transposed bf16 hi/lo (C x V)
// ---------------------------------------------------------------------------
__global__ __launch_bounds__(256) void col_softmax_T(const float* __restrict__ S)
{
    __shared__ float col[V_DIM];
    __shared__ float red[256];
    const int c = blockIdx.x;
    const int tid = threadIdx.x;

    float m = -1e30f;
    for (int v = tid; v < V_DIM; v += 256) {
        float x = S[(size_t)v * C_DIM + c];
        col[v] = x;
        m = fmaxf(m, x);
    }
    red[tid] = m; __syncthreads();
    for (int s = 128; s > 0; s >>= 1) { if (tid < s) red[tid] = fmaxf(red[tid], red[tid + s]); __syncthreads(); }
    m = red[0]; __syncthreads();

    float sum = 0.0f;
    for (int v = tid; v < V_DIM; v += 256) { float e = expf(col[v] - m); col[v] = e; sum += e; }
    red[tid] = sum; __syncthreads();
    for (int s = 128; s > 0; s >>= 1) { if (tid < s) red[tid] += red[tid + s]; __syncthreads(); }
    const float inv = 1.0f / red[0];

    for (int v = tid; v < V_DIM; v += 256) {
        uint16_t h, l;
        split1(col[v] * inv, h, l);
        g_rwTh[(size_t)c * V_DIM + v] = __ushort_as_bfloat16(h);
        g_rwTl[(size_t)c * V_DIM + v] = __ushort_as_bfloat16(l);
    }
}

__global__ __launch_bounds__(256) void prep_wT(const float* __restrict__ W)
{
    int idx = blockIdx.x * 256 + threadIdx.x;
    int op = idx >> 14;
    int rem = idx & 16383;
    int n = rem >> 7, k = rem & 127;
    uint16_t h, l;
    split1(W[op * 16384 + k * 128 + n], h, l);
    g_wTh[idx] = __ushort_as_bfloat16(h);
    g_wTl[idx] = __ushort_as_bfloat16(l);
}

// ---------------------------------------------------------------------------
// MEGA kernel: per 128-row M-tile, fully fused
//   phase1: values = x @ read_w        (K=4096, bf16 split 3-pass)
//   phase2: mix = sum_i w_i f_i(values @ W_i + b_i)
//   phase3: out = mix @ write_w^T * out_scale
// Dynamic smem 192KB:
//   phase1: [0,64K) A x-tiles hi/lo x2 stages ; [64K,128K) B read_w hi/lo x2
//   phase2/3: [0,128K) W / write_w tiles hi/lo x2 stages
//   [128K,160K) vals/mix hi ; [160K,192K) vals/mix lo   (256B rows, swizzled)
// ---------------------------------------------------------------------------
__global__ __launch_bounds__(256, 1) void mega(
    const float* __restrict__ x, const float* __restrict__ logits,
    const float* __restrict__ bias, float* __restrict__ out,
    const float* __restrict__ oscale)
{
    extern __shared__ char sm[];
    __shared__ float bs[N_OPS * C_DIM];
    const uint32_t sb = smem_u32(sm);
    const int tid = threadIdx.x, lane = tid & 31, wid = tid >> 5;
    const int wr = wid & 3, wc = wid >> 2;          // 4x2 warps, warp tile 32x64
    const int m0 = blockIdx.x * 128;
    const float* xbase = x + (size_t)m0 * V_DIM;

    const uint32_t VH = 131072, VL = 163840;

    // bias + logit softmax
#pragma unroll
    for (int i = 0; i < 4; i++) bs[tid + i * 256] = bias[tid + i * 256];
    float wv[N_OPS];
    float mx = -1e30f;
#pragma unroll
    for (int i = 0; i < N_OPS; i++) { wv[i] = __ldg(&logits[i]); mx = fmaxf(mx, wv[i]); }
    float sumw = 0.0f;
#pragma unroll
    for (int i = 0; i < N_OPS; i++) { wv[i] = expf(wv[i] - mx); sumw += wv[i]; }
#pragma unroll
    for (int i = 0; i < N_OPS; i++) wv[i] /= sumw;

    // ---- fragment index helpers (shared by all phases) ----
    const int arow16 = lane & 15;       // ldmatrix A row within 16
    const int ako = lane >> 4;          // A k-group select
    const int brow8 = ((lane >> 4) & 1) * 8 + (lane & 7);
    const int bko = (lane >> 3) & 1;

    // =========================== PHASE 1 ===========================
    {
        float4 apf[8];
        float acc[2][8][4];
#pragma unroll
        for (int a = 0; a < 2; a++)
#pragma unroll
            for (int b = 0; b < 8; b++)
#pragma unroll
                for (int c = 0; c < 4; c++) acc[a][b][c] = 0.0f;

        auto ldA = [&](int k0) {
#pragma unroll
            for (int i = 0; i < 8; i++) {
                int idx = tid + i * 256;
                apf[i] = *(const float4*)&xbase[(size_t)(idx >> 4) * V_DIM + k0 + (idx & 15) * 4];
            }
        };
        auto stA = [&](int s) {
            char* ah = sm + s * 32768;
            char* al = sm + s * 32768 + 16384;
#pragma unroll
            for (int i = 0; i < 8; i++) {
                int idx = tid + i * 256;
                int r = idx >> 4, c4 = idx & 15;
                uint32_t h0, l0, h1, l1;
                split2(apf[i].x, apf[i].y, h0, l0);
                split2(apf[i].z, apf[i].w, h1, l1);
                uint32_t so = r * 128 + ((uint32_t)((c4 >> 1) ^ (r & 7)) << 4) + (c4 & 1) * 8;
                *(uint2*)(ah + so) = make_uint2(h0, h1);
                *(uint2*)(al + so) = make_uint2(l0, l1);
            }
        };
        auto ldB = [&](int k0, int s) {
            uint32_t bh = sb + 65536 + s * 32768;
            uint32_t bl = sb + 65536 + s * 32768 + 16384;
#pragma unroll
            for (int i = 0; i < 4; i++) {
                int idx = tid + i * 256;
                int r = idx >> 3, c = idx & 7;
                uint32_t so = r * 128 + ((uint32_t)(c ^ (r & 7)) << 4);
                CP16(bh + so, &g_rwTh[(size_t)r * V_DIM + k0 + c * 8]);
                CP16(bl + so, &g_rwTl[(size_t)r * V_DIM + k0 + c * 8]);
            }
        };

        ldA(0);
        ldB(0, 0); CP_COMMIT();

        for (int ch = 0; ch < 64; ch++) {
            const int s = ch & 1;
            stA(s);
            if (ch < 63) {
                ldA((ch + 1) * 64);
                ldB((ch + 1) * 64, 1 - s); CP_COMMIT();
                cp_wait<1>();
            } else {
                cp_wait<0>();
            }
            __syncthreads();

            const uint32_t ah0 = sb + s * 32768;
            const uint32_t al0 = sb + s * 32768 + 16384;
            const uint32_t bh0 = sb + 65536 + s * 32768;
            const uint32_t bl0 = sb + 65536 + s * 32768 + 16384;
#pragma unroll
            for (int ks = 0; ks < 4; ks++) {
                uint32_t Ah[2][4], Al[2][4], Bh[8][2], Bl[8][2];
#pragma unroll
                for (int mf = 0; mf < 2; mf++) {
                    uint32_t rr = wr * 32 + mf * 16 + arow16;
                    uint32_t so = rr * 128 + ((uint32_t)((ks * 2 + ako) ^ (rr & 7)) << 4);
                    ldsm4(Ah[mf][0], Ah[mf][1], Ah[mf][2], Ah[mf][3], ah0 + so);
                    ldsm4(Al[mf][0], Al[mf][1], Al[mf][2], Al[mf][3], al0 + so);
                }
#pragma unroll
                for (int p = 0; p < 4; p++) {
                    uint32_t rr = wc * 64 + brow8 + p * 16;
                    uint32_t so = rr * 128 + ((uint32_t)((ks * 2 + bko) ^ (rr & 7)) << 4);
                    ldsm4(Bh[2 * p][0], Bh[2 * p][1], Bh[2 * p + 1][0], Bh[2 * p + 1][1], bh0 + so);
                    ldsm4(Bl[2 * p][0], Bl[2 * p][1], Bl[2 * p + 1][0], Bl[2 * p + 1][1], bl0 + so);
                }
#pragma unroll
                for (int mf = 0; mf < 2; mf++)
#pragma unroll
                    for (int nf = 0; nf < 8; nf++) {
                        mma_bf16(acc[mf][nf], Ah[mf], Bh[nf]);
                        mma_bf16(acc[mf][nf], Ah[mf], Bl[nf]);
                        mma_bf16(acc[mf][nf], Al[mf], Bh[nf]);
                    }
            }
            __syncthreads();
        }

        // prefetch op0 weights (into [0,64K), free now)
        {
            uint32_t wh = sb, wl = sb + 32768;
#pragma unroll
            for (int i = 0; i < 8; i++) {
                int idx = tid + i * 256;
                int r = idx >> 4, c16 = idx & 15;
                uint32_t so = r * 256 + ((uint32_t)(c16 ^ (r & 7)) << 4);
                CP16(wh + so, &g_wTh[r * C_DIM + c16 * 8]);
                CP16(wl + so, &g_wTl[r * C_DIM + c16 * 8]);
            }
            CP_COMMIT();
        }

        // vals -> smem (bf16 hi/lo, 256B swizzled rows)
#pragma unroll
        for (int mf = 0; mf < 2; mf++)
#pragma unroll
            for (int nf = 0; nf < 8; nf++) {
                int r = wr * 32 + mf * 16 + (lane >> 2);
                int c = wc * 64 + nf * 8 + 2 * (lane & 3);
                uint32_t h0, l0, h1, l1;
                split2(acc[mf][nf][0], acc[mf][nf][1], h0, l0);
                split2(acc[mf][nf][2], acc[mf][nf][3], h1, l1);
                uint32_t so0 = r * 256 + ((uint32_t)((c >> 3) ^ (r & 7)) << 4) + ((c & 7) << 1);
                uint32_t so1 = (r + 8) * 256 + ((uint32_t)((c >> 3) ^ ((r + 8) & 7)) << 4) + ((c & 7) << 1);
                *(uint32_t*)(sm + VH + so0) = h0;
                *(uint32_t*)(sm + VL + so0) = l0;
                *(uint32_t*)(sm + VH + so1) = h1;
                *(uint32_t*)(sm + VL + so1) = l1;
            }
        __syncthreads();
    }

    // =========================== PHASE 2 ===========================
    float res[2][8][4];
#pragma unroll
    for (int a = 0; a < 2; a++)
#pragma unroll
        for (int b = 0; b < 8; b++)
#pragma unroll
            for (int c = 0; c < 4; c++) res[a][b][c] = 0.0f;

    {
        auto ldW = [&](int op, int s) {
            uint32_t wh = sb + s * 65536;
            uint32_t wl = sb + s * 65536 + 32768;
#pragma unroll
            for (int i = 0; i < 8; i++) {
                int idx = tid + i * 256;
                int r = idx >> 4, c16 = idx & 15;
                uint32_t so = r * 256 + ((uint32_t)(c16 ^ (r & 7)) << 4);
                CP16(wh + so, &g_wTh[(size_t)op * 16384 + r * C_DIM + c16 * 8]);
                CP16(wl + so, &g_wTl[(size_t)op * 16384 + r * C_DIM + c16 * 8]);
            }
        };

#pragma unroll 1
        for (int op = 0; op < N_OPS; op++) {
            const int s = op & 1;
            if (op < 7) { ldW(op + 1, 1 - s); CP_COMMIT(); cp_wait<1>(); }
            else cp_wait<0>();
            __syncthreads();

            float acc[2][8][4];
#pragma unroll
            for (int a = 0; a < 2; a++)
#pragma unroll
                for (int b = 0; b < 8; b++)
#pragma unroll
                    for (int c = 0; c < 4; c++) acc[a][b][c] = 0.0f;

            const uint32_t wh0 = sb + s * 65536;
            const uint32_t wl0 = sb + s * 65536 + 32768;
#pragma unroll
            for (int ks = 0; ks < 8; ks++) {
                uint32_t Ah[2][4], Al[2][4], Bh[8][2], Bl[8][2];
#pragma unroll
                for (int mf = 0; mf < 2; mf++) {
                    uint32_t rr = wr * 32 + mf * 16 + arow16;
                    uint32_t so = rr * 256 + ((uint32_t)((ks * 2 + ako) ^ (rr & 7)) << 4);
                    ldsm4(Ah[mf][0], Ah[mf][1], Ah[mf][2], Ah[mf][3], sb + VH + so);
                    ldsm4(Al[mf][0], Al[mf][1], Al[mf][2], Al[mf][3], sb + VL + so);
                }
#pragma unroll
                for (int p = 0; p < 4; p++) {
                    uint32_t rr = wc * 64 + brow8 + p * 16;
                    uint32_t so = rr * 256 + ((uint32_t)((ks * 2 + bko) ^ (rr & 7)) << 4);
                    ldsm4(Bh[2 * p][0], Bh[2 * p][1], Bh[2 * p + 1][0], Bh[2 * p + 1][1], wh0 + so);
                    ldsm4(Bl[2 * p][0], Bl[2 * p][1], Bl[2 * p + 1][0], Bl[2 * p + 1][1], wl0 + so);
                }
#pragma unroll
                for (int mf = 0; mf < 2; mf++)
#pragma unroll
                    for (int nf = 0; nf < 8; nf++) {
                        mma_bf16(acc[mf][nf], Ah[mf], Bh[nf]);
                        mma_bf16(acc[mf][nf], Ah[mf], Bl[nf]);
                        mma_bf16(acc[mf][nf], Al[mf], Bh[nf]);
                    }
            }
            const float w = wv[op];
#pragma unroll
            for (int mf = 0; mf < 2; mf++)
#pragma unroll
                for (int nf = 0; nf < 8; nf++)
#pragma unroll
                    for (int j = 0; j < 4; j++) {
                        int col = wc * 64 + nf * 8 + 2 * (lane & 3) + (j & 1);
                        float v = acc[mf][nf][j] + bs[op * C_DIM + col];
                        float f;
                        switch (op) {
                            case 0: f = v; break;
                            case 1: f = fmaxf(v, 0.0f); break;
                            case 2: f = 0.5f * v * (1.0f + erff(v * 0.70710678118654752f)); break;
                            case 3: f = v * v; break;
                            case 4: f = -v; break;
                            case 5: f = fabsf(v); break;
                            case 6: f = tanhf(v); break;
                            default: f = 1.0f / (1.0f + expf(-v)); break;
                        }
                        res[mf][nf][j] += w * f;
                    }
            __syncthreads();
        }
    }

    // prefetch first write_w tile (into stage 0, free after op6 sync)
    {
        uint32_t bh = sb, bl = sb + 32768;
#pragma unroll
        for (int i = 0; i < 8; i++) {
            int idx = tid + i * 256;
            int r = idx >> 4, c16 = idx & 15;
            uint32_t so = r * 256 + ((uint32_t)(c16 ^ (r & 7)) << 4);
            CP16(bh + so, &g_wwh[(size_t)r * C_DIM + c16 * 8]);
            CP16(bl + so, &g_wwl[(size_t)r * C_DIM + c16 * 8]);
        }
        CP_COMMIT();
    }

    // mix -> smem (overwrite vals region; all vals reads done)
#pragma unroll
    for (int mf = 0; mf < 2; mf++)
#pragma unroll
        for (int nf = 0; nf < 8; nf++) {
            int r = wr * 32 + mf * 16 + (lane >> 2);
            int c = wc * 64 + nf * 8 + 2 * (lane & 3);
            uint32_t h0, l0, h1, l1;
            split2(res[mf][nf][0], res[mf][nf][1], h0, l0);
            split2(res[mf][nf][2], res[mf][nf][3], h1, l1);
            uint32_t so0 = r * 256 + ((uint32_t)((c >> 3) ^ (r & 7)) << 4) + ((c & 7) << 1);
            uint32_t so1 = (r + 8) * 256 + ((uint32_t)((c >> 3) ^ ((r + 8) & 7)) << 4) + ((c & 7) << 1);
            *(uint32_t*)(sm + VH + so0) = h0;
            *(uint32_t*)(sm + VL + so0) = l0;
            *(uint32_t*)(sm + VH + so1) = h1;
            *(uint32_t*)(sm + VL + so1) = l1;
        }
    __syncthreads();

    // =========================== PHASE 3 ===========================
    {
        const float alpha = __ldg(oscale);
        auto ldB2 = [&](int n0, int s) {
            uint32_t bh = sb + s * 65536;
            uint32_t bl = sb + s * 65536 + 32768;
#pragma unroll
            for (int i = 0; i < 8; i++) {
                int idx = tid + i * 256;
                int r = idx >> 4, c16 = idx & 15;
                uint32_t so = r * 256 + ((uint32_t)(c16 ^ (r & 7)) << 4);
                CP16(bh + so, &g_wwh[(size_t)(n0 + r) * C_DIM + c16 * 8]);
                CP16(bl + so, &g_wwl[(size_t)(n0 + r) * C_DIM + c16 * 8]);
            }
        };

#pragma unroll 1
        for (int nt = 0; nt < 32; nt++) {
            const int s = nt & 1;
            if (nt < 31) { ldB2((nt + 1) * 128, 1 - s); CP_COMMIT(); cp_wait<1>(); }
            else cp_wait<0>();
            __syncthreads();

            float acc[2][8][4];
#pragma unroll
            for (int a = 0; a < 2; a++)
#pragma unroll
                for (int b = 0; b < 8; b++)
#pragma unroll
                    for (int c = 0; c < 4; c++) acc[a][b][c] = 0.0f;

            const uint32_t bh0 = sb + s * 65536;
            const uint32_t bl0 = sb + s * 65536 + 32768;
#pragma unroll
            for (int ks = 0; ks < 8; ks++) {
                uint32_t Ah[2][4], Al[2][4], Bh[8][2], Bl[8][2];
#pragma unroll
                for (int mf = 0; mf < 2; mf++) {
                    uint32_t rr = wr * 32 + mf * 16 + arow16;
                    uint32_t so = rr * 256 + ((uint32_t)((ks * 2 + ako) ^ (rr & 7)) << 4);
                    ldsm4(Ah[mf][0], Ah[mf][1], Ah[mf][2], Ah[mf][3], sb + VH + so);
                    ldsm4(Al[mf][0], Al[mf][1], Al[mf][2], Al[mf][3], sb + VL + so);
                }
#pragma unroll
                for (int p = 0; p < 4; p++) {
                    uint32_t rr = wc * 64 + brow8 + p * 16;
                    uint32_t so = rr * 256 + ((uint32_t)((ks * 2 + bko) ^ (rr & 7)) << 4);
                    ldsm4(Bh[2 * p][0], Bh[2 * p][1], Bh[2 * p + 1][0], Bh[2 * p + 1][1], bh0 + so);
                    ldsm4(Bl[2 * p][0], Bl[2 * p][1], Bl[2 * p + 1][0], Bl[2 * p + 1][1], bl0 + so);
                }
#pragma unroll
                for (int mf = 0; mf < 2; mf++)
#pragma unroll
                    for (int nf = 0; nf < 8; nf++) {
                        mma_bf16(acc[mf][nf], Ah[mf], Bh[nf]);
                        mma_bf16(acc[mf][nf], Ah[mf], Bl[nf]);
                        mma_bf16(acc[mf][nf], Al[mf], Bh[nf]);
                    }
            }
#pragma unroll
            for (int mf = 0; mf < 2; mf++)
#pragma unroll
                for (int nf = 0; nf < 8; nf++) {
                    int r = m0 + wr * 32 + mf * 16 + (lane >> 2);
                    int c = nt * 128 + wc * 64 + nf * 8 + 2 * (lane & 3);
                    float2 v0 = make_float2(acc[mf][nf][0] * alpha, acc[mf][nf][1] * alpha);
                    float2 v1 = make_float2(acc[mf][nf][2] * alpha, acc[mf][nf][3] * alpha);
                    *(float2*)&out[(size_t)r * V_DIM + c] = v0;
                    *(float2*)&out[(size_t)(r + 8) * V_DIM + c] = v1;
                }
            __syncthreads();
        }
    }
}

// ---------------------------------------------------------------------------
extern "C" void kernel_launch(void* const* d_in, const int* in_sizes, int n_in,
                              void* d_out, int out_size)
{
    const float* x      = (const float*)d_in[0];
    const float* basis  = (const float*)d_in[1];
    const float* rcoef  = (const float*)d_in[2];
    const float* wcoef  = (const float*)d_in[3];
    const float* logits = (const float*)d_in[4];
    const float* opW    = (const float*)d_in[5];
    const float* opB    = (const float*)d_in[6];
    const float* oscale = (const float*)d_in[7];
    float* out = (float*)d_out;

    float* p_rw;
    cudaGetSymbolAddress((void**)&p_rw, g_rw);

    static bool attr_done = false;
    if (!attr_done) {
        cudaFuncSetAttribute(mega, cudaFuncAttributeMaxDynamicSharedMemorySize, 196608);
        attr_done = true;
    }

    // 1) addressing scores: z=0 read (fp32), z=1 write (split bf16)
    sgemm_addr<<<dim3(1, V_DIM / 128, 2), 256>>>(basis, rcoef, wcoef);
    // 2) read softmax + transpose + split; op weights transpose + split
    col_softmax_T<<<C_DIM, 256>>>(p_rw);
    prep_wT<<<N_OPS * C_DIM * C_DIM / 256, 256>>>(opW);
    // 3) fused pipeline
    mega<<<M_TOK / 128, 256, 196608>>>(x, logits, opB, out, oscale);
}

// round 11
// speedup vs baseline: 1.0481x; 1.0481x over previous
#include <cuda_runtime.h>
#include <cuda_bf16.h>
#include <math.h>
#include <stdint.h>

#define M_TOK 16384
#define V_DIM 4096
#define C_DIM 128
#define K_NB2 128
#define N_OPS 8

// ------------------------- scratch (device globals) -------------------------
__device__ float g_rw[V_DIM * C_DIM];                  // read scores fp32
__device__ __nv_bfloat16 g_rwTh[C_DIM * V_DIM];        // read_w^T hi (C x V)
__device__ __nv_bfloat16 g_rwTl[C_DIM * V_DIM];
__device__ __nv_bfloat16 g_wwh[V_DIM * C_DIM];         // write_w hi (V x C)
__device__ __nv_bfloat16 g_wwl[V_DIM * C_DIM];
__device__ __nv_bfloat16 g_wTh[N_OPS * C_DIM * C_DIM]; // op W^T [op][n][k]
__device__ __nv_bfloat16 g_wTl[N_OPS * C_DIM * C_DIM];

// ------------------------- helpers -------------------------
__device__ __forceinline__ uint32_t smem_u32(const void* p) {
    uint32_t a;
    asm("{ .reg .u64 t; cvta.to.shared.u64 t, %1; cvt.u32.u64 %0, t; }" : "=r"(a) : "l"(p));
    return a;
}
#define CP16(saddr, gptr) \
    asm volatile("cp.async.cg.shared.global [%0], [%1], 16;" :: "r"(saddr), "l"(gptr) : "memory")
#define CP_COMMIT() asm volatile("cp.async.commit_group;" ::: "memory")
template <int N> __device__ __forceinline__ void cp_wait() {
    asm volatile("cp.async.wait_group %0;" :: "n"(N) : "memory");
}
__device__ __forceinline__ void ldsm4(uint32_t& r0, uint32_t& r1, uint32_t& r2, uint32_t& r3, uint32_t a) {
    asm volatile("ldmatrix.sync.aligned.m8n8.x4.shared.b16 {%0,%1,%2,%3}, [%4];"
        : "=r"(r0), "=r"(r1), "=r"(r2), "=r"(r3) : "r"(a));
}
__device__ __forceinline__ void mma_bf16(float c[4], const uint32_t a[4], const uint32_t b[2]) {
    asm volatile(
        "mma.sync.aligned.m16n8k16.row.col.f32.bf16.bf16.f32 "
        "{%0,%1,%2,%3},{%4,%5,%6,%7},{%8,%9},{%0,%1,%2,%3};"
        : "+f"(c[0]), "+f"(c[1]), "+f"(c[2]), "+f"(c[3])
        : "r"(a[0]), "r"(a[1]), "r"(a[2]), "r"(a[3]), "r"(b[0]), "r"(b[1]));
}
__device__ __forceinline__ void split2(float a, float b, uint32_t& hi, uint32_t& lo) {
    __nv_bfloat16 ha = __float2bfloat16(a), hb = __float2bfloat16(b);
    __nv_bfloat16 la = __float2bfloat16(a - __bfloat162float(ha));
    __nv_bfloat16 lb = __float2bfloat16(b - __bfloat162float(hb));
    hi = (uint32_t)__bfloat16_as_ushort(ha) | ((uint32_t)__bfloat16_as_ushort(hb) << 16);
    lo = (uint32_t)__bfloat16_as_ushort(la) | ((uint32_t)__bfloat16_as_ushort(lb) << 16);
}
__device__ __forceinline__ void split1(float a, uint16_t& h, uint16_t& l) {
    __nv_bfloat16 ha = __float2bfloat16(a);
    __nv_bfloat16 la = __float2bfloat16(a - __bfloat162float(ha));
    h = __bfloat16_as_ushort(ha);
    l = __bfloat16_as_ushort(la);
}

// ---------------------------------------------------------------------------
// Addressing GEMM: scores = basis(4096x128) @ coeff(128x128)^T
// z=0: rcoef -> g_rw fp32;  z=1: wcoef -> split to g_wwh/g_wwl
// ---------------------------------------------------------------------------
__global__ __launch_bounds__(256) void sgemm_addr(
    const float* __restrict__ A, const float* __restrict__ B0,
    const float* __restrict__ B1)
{
    __shared__ float As[16][128];
    __shared__ float Bs[16][128];
    const int tid = threadIdx.x;
    const int tc = tid % 16, tr = tid / 16;
    const int m0 = blockIdx.y * 128;
    const int path = blockIdx.z;
    const float* B = path ? B1 : B0;

    float acc[8][8];
#pragma unroll
    for (int i = 0; i < 8; i++)
#pragma unroll
        for (int j = 0; j < 8; j++) acc[i][j] = 0.0f;

    for (int k0 = 0; k0 < K_NB2; k0 += 16) {
#pragma unroll
        for (int i = 0; i < 2; i++) {
            int idx = tid + i * 256;
            int row = idx / 4, c4 = idx % 4;
            float4 va = *(const float4*)&A[(size_t)(m0 + row) * K_NB2 + k0 + c4 * 4];
            As[c4 * 4 + 0][row] = va.x; As[c4 * 4 + 1][row] = va.y;
            As[c4 * 4 + 2][row] = va.z; As[c4 * 4 + 3][row] = va.w;
            float4 vb = *(const float4*)&B[(size_t)row * K_NB2 + k0 + c4 * 4];
            Bs[c4 * 4 + 0][row] = vb.x; Bs[c4 * 4 + 1][row] = vb.y;
            Bs[c4 * 4 + 2][row] = vb.z; Bs[c4 * 4 + 3][row] = vb.w;
        }
        __syncthreads();
#pragma unroll
        for (int k = 0; k < 16; k++) {
            float ra[8], rb[8];
#pragma unroll
            for (int i = 0; i < 8; i++) ra[i] = As[k][tr * 8 + i];
#pragma unroll
            for (int j = 0; j < 8; j++) rb[j] = Bs[k][tc * 8 + j];
#pragma unroll
            for (int i = 0; i < 8; i++)
#pragma unroll
                for (int j = 0; j < 8; j++) acc[i][j] += ra[i] * rb[j];
        }
        __syncthreads();
    }
#pragma unroll
    for (int i = 0; i < 8; i++) {
        const size_t base = (size_t)(m0 + tr * 8 + i) * C_DIM + tc * 8;
        if (path == 0) {
#pragma unroll
            for (int j = 0; j < 8; j++) g_rw[base + j] = acc[i][j];
        } else {
#pragma unroll
            for (int j = 0; j < 8; j++) {
                uint16_t h, l;
                split1(acc[i][j], h, l);
                g_wwh[base + j] = __ushort_as_bfloat16(h);
                g_wwl[base + j] = __ushort_as_bfloat16(l);
            }
        }
    }
}

// ---------------------------------------------------------------------------
// Column softmax over V (axis 0); write transposed bf16 hi/lo (C x V)
// ---------------------------------------------------------------------------
__global__ __launch_bounds__(256) void col_softmax_T(const float* __restrict__ S)
{
    __shared__ float col[V_DIM];
    __shared__ float red[256];
    const int c = blockIdx.x;
    const int tid = threadIdx.x;

    float m = -1e30f;
    for (int v = tid; v < V_DIM; v += 256) {
        float x = S[(size_t)v * C_DIM + c];
        col[v] = x;
        m = fmaxf(m, x);
    }
    red[tid] = m; __syncthreads();
    for (int s = 128; s > 0; s >>= 1) { if (tid < s) red[tid] = fmaxf(red[tid], red[tid + s]); __syncthreads(); }
    m = red[0]; __syncthreads();

    float sum = 0.0f;
    for (int v = tid; v < V_DIM; v += 256) { float e = expf(col[v] - m); col[v] = e; sum += e; }
    red[tid] = sum; __syncthreads();
    for (int s = 128; s > 0; s >>= 1) { if (tid < s) red[tid] += red[tid + s]; __syncthreads(); }
    const float inv = 1.0f / red[0];

    for (int v = tid; v < V_DIM; v += 256) {
        uint16_t h, l;
        split1(col[v] * inv, h, l);
        g_rwTh[(size_t)c * V_DIM + v] = __ushort_as_bfloat16(h);
        g_rwTl[(size_t)c * V_DIM + v] = __ushort_as_bfloat16(l);
    }
}

__global__ __launch_bounds__(256) void prep_wT(const float* __restrict__ W)
{
    int idx = blockIdx.x * 256 + threadIdx.x;
    int op = idx >> 14;
    int rem = idx & 16383;
    int n = rem >> 7, k = rem & 127;
    uint16_t h, l;
    split1(W[op * 16384 + k * 128 + n], h, l);
    g_wTh[idx] = __ushort_as_bfloat16(h);
    g_wTl[idx] = __ushort_as_bfloat16(l);
}

// ---------------------------------------------------------------------------
// MEGA kernel, 512 threads (16 warps, 4x4 warp grid, warp tile 32x32):
//   phase1: values = x @ read_w        (K=4096, bf16 split 3-pass)
//   phase2: mix = sum_i w_i f_i(values @ W_i + b_i)
//   phase3: out = mix @ write_w^T * out_scale
// Dynamic smem 192KB:
//   phase1: [0,64K) A x-tiles hi/lo x2 stages ; [64K,128K) B read_w hi/lo x2
//   phase2/3: [0,128K) W / write_w tiles hi/lo x2 stages
//   [128K,160K) vals/mix hi ; [160K,192K) vals/mix lo  (256B rows, swizzled)
// ---------------------------------------------------------------------------
__global__ __launch_bounds__(512, 1) void mega(
    const float* __restrict__ x, const float* __restrict__ logits,
    const float* __restrict__ bias, float* __restrict__ out,
    const float* __restrict__ oscale)
{
    extern __shared__ char sm[];
    __shared__ float bs[N_OPS * C_DIM];
    const uint32_t sb = smem_u32(sm);
    const int tid = threadIdx.x, lane = tid & 31, wid = tid >> 5;
    const int wr = wid & 3, wc = wid >> 2;          // 4x4 warps, warp tile 32x32
    const int m0 = blockIdx.x * 128;
    const float* xbase = x + (size_t)m0 * V_DIM;

    const uint32_t VH = 131072, VL = 163840;

    // bias + logit softmax
#pragma unroll
    for (int i = 0; i < 2; i++) bs[tid + i * 512] = bias[tid + i * 512];
    float wv[N_OPS];
    float mx = -1e30f;
#pragma unroll
    for (int i = 0; i < N_OPS; i++) { wv[i] = __ldg(&logits[i]); mx = fmaxf(mx, wv[i]); }
    float sumw = 0.0f;
#pragma unroll
    for (int i = 0; i < N_OPS; i++) { wv[i] = expf(wv[i] - mx); sumw += wv[i]; }
#pragma unroll
    for (int i = 0; i < N_OPS; i++) wv[i] /= sumw;

    // fragment index helpers
    const int arow16 = lane & 15;
    const int ako = lane >> 4;
    const int brow8 = ((lane >> 4) & 1) * 8 + (lane & 7);
    const int bko = (lane >> 3) & 1;

    // =========================== PHASE 1 ===========================
    {
        float4 apf[4];
        float acc[2][4][4];
#pragma unroll
        for (int a = 0; a < 2; a++)
#pragma unroll
            for (int b = 0; b < 4; b++)
#pragma unroll
                for (int c = 0; c < 4; c++) acc[a][b][c] = 0.0f;

        auto ldA = [&](int k0) {
#pragma unroll
            for (int i = 0; i < 4; i++) {
                int idx = tid + i * 512;
                apf[i] = *(const float4*)&xbase[(size_t)(idx >> 4) * V_DIM + k0 + (idx & 15) * 4];
            }
        };
        auto stA = [&](int s) {
            char* ah = sm + s * 32768;
            char* al = sm + s * 32768 + 16384;
#pragma unroll
            for (int i = 0; i < 4; i++) {
                int idx = tid + i * 512;
                int r = idx >> 4, c4 = idx & 15;
                uint32_t h0, l0, h1, l1;
                split2(apf[i].x, apf[i].y, h0, l0);
                split2(apf[i].z, apf[i].w, h1, l1);
                uint32_t so = r * 128 + ((uint32_t)((c4 >> 1) ^ (r & 7)) << 4) + (c4 & 1) * 8;
                *(uint2*)(ah + so) = make_uint2(h0, h1);
                *(uint2*)(al + so) = make_uint2(l0, l1);
            }
        };
        auto ldB = [&](int k0, int s) {
            uint32_t bh = sb + 65536 + s * 32768;
            uint32_t bl = sb + 65536 + s * 32768 + 16384;
#pragma unroll
            for (int i = 0; i < 2; i++) {
                int idx = tid + i * 512;
                int r = idx >> 3, c = idx & 7;
                uint32_t so = r * 128 + ((uint32_t)(c ^ (r & 7)) << 4);
                CP16(bh + so, &g_rwTh[(size_t)r * V_DIM + k0 + c * 8]);
                CP16(bl + so, &g_rwTl[(size_t)r * V_DIM + k0 + c * 8]);
            }
        };

        ldA(0);
        ldB(0, 0); CP_COMMIT();

        for (int ch = 0; ch < 64; ch++) {
            const int s = ch & 1;
            stA(s);
            if (ch < 63) {
                ldA((ch + 1) * 64);
                ldB((ch + 1) * 64, 1 - s); CP_COMMIT();
                cp_wait<1>();
            } else {
                cp_wait<0>();
            }
            __syncthreads();

            const uint32_t ah0 = sb + s * 32768;
            const uint32_t al0 = sb + s * 32768 + 16384;
            const uint32_t bh0 = sb + 65536 + s * 32768;
            const uint32_t bl0 = sb + 65536 + s * 32768 + 16384;
#pragma unroll
            for (int ks = 0; ks < 4; ks++) {
                uint32_t Ah[2][4], Al[2][4], Bh[4][2], Bl[4][2];
#pragma unroll
                for (int mf = 0; mf < 2; mf++) {
                    uint32_t rr = wr * 32 + mf * 16 + arow16;
                    uint32_t so = rr * 128 + ((uint32_t)((ks * 2 + ako) ^ (rr & 7)) << 4);
                    ldsm4(Ah[mf][0], Ah[mf][1], Ah[mf][2], Ah[mf][3], ah0 + so);
                    ldsm4(Al[mf][0], Al[mf][1], Al[mf][2], Al[mf][3], al0 + so);
                }
#pragma unroll
                for (int p = 0; p < 2; p++) {
                    uint32_t rr = wc * 32 + brow8 + p * 16;
                    uint32_t so = rr * 128 + ((uint32_t)((ks * 2 + bko) ^ (rr & 7)) << 4);
                    ldsm4(Bh[2 * p][0], Bh[2 * p][1], Bh[2 * p + 1][0], Bh[2 * p + 1][1], bh0 + so);
                    ldsm4(Bl[2 * p][0], Bl[2 * p][1], Bl[2 * p + 1][0], Bl[2 * p + 1][1], bl0 + so);
                }
#pragma unroll
                for (int mf = 0; mf < 2; mf++)
#pragma unroll
                    for (int nf = 0; nf < 4; nf++) {
                        mma_bf16(acc[mf][nf], Ah[mf], Bh[nf]);
                        mma_bf16(acc[mf][nf], Ah[mf], Bl[nf]);
                        mma_bf16(acc[mf][nf], Al[mf], Bh[nf]);
                    }
            }
            __syncthreads();
        }

        // prefetch op0 weights (into [0,64K), free now)
        {
            uint32_t wh = sb, wl = sb + 32768;
#pragma unroll
            for (int i = 0; i < 4; i++) {
                int idx = tid + i * 512;
                int r = idx >> 4, c16 = idx & 15;
                uint32_t so = r * 256 + ((uint32_t)(c16 ^ (r & 7)) << 4);
                CP16(wh + so, &g_wTh[r * C_DIM + c16 * 8]);
                CP16(wl + so, &g_wTl[r * C_DIM + c16 * 8]);
            }
            CP_COMMIT();
        }

        // vals -> smem (bf16 hi/lo, 256B swizzled rows)
#pragma unroll
        for (int mf = 0; mf < 2; mf++)
#pragma unroll
            for (int nf = 0; nf < 4; nf++) {
                int r = wr * 32 + mf * 16 + (lane >> 2);
                int c = wc * 32 + nf * 8 + 2 * (lane & 3);
                uint32_t h0, l0, h1, l1;
                split2(acc[mf][nf][0], acc[mf][nf][1], h0, l0);
                split2(acc[mf][nf][2], acc[mf][nf][3], h1, l1);
                uint32_t so0 = r * 256 + ((uint32_t)((c >> 3) ^ (r & 7)) << 4) + ((c & 7) << 1);
                uint32_t so1 = (r + 8) * 256 + ((uint32_t)((c >> 3) ^ ((r + 8) & 7)) << 4) + ((c & 7) << 1);
                *(uint32_t*)(sm + VH + so0) = h0;
                *(uint32_t*)(sm + VL + so0) = l0;
                *(uint32_t*)(sm + VH + so1) = h1;
                *(uint32_t*)(sm + VL + so1) = l1;
            }
        __syncthreads();
    }

    // =========================== PHASE 2 ===========================
    float res[2][4][4];
#pragma unroll
    for (int a = 0; a < 2; a++)
#pragma unroll
        for (int b = 0; b < 4; b++)
#pragma unroll
            for (int c = 0; c < 4; c++) res[a][b][c] = 0.0f;

    {
        auto ldW = [&](int op, int s) {
            uint32_t wh = sb + s * 65536;
            uint32_t wl = sb + s * 65536 + 32768;
#pragma unroll
            for (int i = 0; i < 4; i++) {
                int idx = tid + i * 512;
                int r = idx >> 4, c16 = idx & 15;
                uint32_t so = r * 256 + ((uint32_t)(c16 ^ (r & 7)) << 4);
                CP16(wh + so, &g_wTh[(size_t)op * 16384 + r * C_DIM + c16 * 8]);
                CP16(wl + so, &g_wTl[(size_t)op * 16384 + r * C_DIM + c16 * 8]);
            }
        };

#pragma unroll 1
        for (int op = 0; op < N_OPS; op++) {
            const int s = op & 1;
            if (op < 7) { ldW(op + 1, 1 - s); CP_COMMIT(); cp_wait<1>(); }
            else cp_wait<0>();
            __syncthreads();

            float acc[2][4][4];
#pragma unroll
            for (int a = 0; a < 2; a++)
#pragma unroll
                for (int b = 0; b < 4; b++)
#pragma unroll
                    for (int c = 0; c < 4; c++) acc[a][b][c] = 0.0f;

            const uint32_t wh0 = sb + s * 65536;
            const uint32_t wl0 = sb + s * 65536 + 32768;
#pragma unroll
            for (int ks = 0; ks < 8; ks++) {
                uint32_t Ah[2][4], Al[2][4], Bh[4][2], Bl[4][2];
#pragma unroll
                for (int mf = 0; mf < 2; mf++) {
                    uint32_t rr = wr * 32 + mf * 16 + arow16;
                    uint32_t so = rr * 256 + ((uint32_t)((ks * 2 + ako) ^ (rr & 7)) << 4);
                    ldsm4(Ah[mf][0], Ah[mf][1], Ah[mf][2], Ah[mf][3], sb + VH + so);
                    ldsm4(Al[mf][0], Al[mf][1], Al[mf][2], Al[mf][3], sb + VL + so);
                }
#pragma unroll
                for (int p = 0; p < 2; p++) {
                    uint32_t rr = wc * 32 + brow8 + p * 16;
                    uint32_t so = rr * 256 + ((uint32_t)((ks * 2 + bko) ^ (rr & 7)) << 4);
                    ldsm4(Bh[2 * p][0], Bh[2 * p][1], Bh[2 * p + 1][0], Bh[2 * p + 1][1], wh0 + so);
                    ldsm4(Bl[2 * p][0], Bl[2 * p][1], Bl[2 * p + 1][0], Bl[2 * p + 1][1], wl0 + so);
                }
#pragma unroll
                for (int mf = 0; mf < 2; mf++)
#pragma unroll
                    for (int nf = 0; nf < 4; nf++) {
                        mma_bf16(acc[mf][nf], Ah[mf], Bh[nf]);
                        mma_bf16(acc[mf][nf], Ah[mf], Bl[nf]);
                        mma_bf16(acc[mf][nf], Al[mf], Bh[nf]);
                    }
            }
            const float w = wv[op];
#pragma unroll
            for (int mf = 0; mf < 2; mf++)
#pragma unroll
                for (int nf = 0; nf < 4; nf++)
#pragma unroll
                    for (int j = 0; j < 4; j++) {
                        int col = wc * 32 + nf * 8 + 2 * (lane & 3) + (j & 1);
                        float v = acc[mf][nf][j] + bs[op * C_DIM + col];
                        float f;
                        switch (op) {
                            case 0: f = v; break;
                            case 1: f = fmaxf(v, 0.0f); break;
                            case 2: f = 0.5f * v * (1.0f + erff(v * 0.70710678118654752f)); break;
                            case 3: f = v * v; break;
                            case 4: f = -v; break;
                            case 5: f = fabsf(v); break;
                            case 6: f = tanhf(v); break;
                            default: f = 1.0f / (1.0f + expf(-v)); break;
                        }
                        res[mf][nf][j] += w * f;
                    }
            __syncthreads();
        }
    }

    // prefetch first write_w tile (into stage 0, free now)
    {
        uint32_t bh = sb, bl = sb + 32768;
#pragma unroll
        for (int i = 0; i < 4; i++) {
            int idx = tid + i * 512;
            int r = idx >> 4, c16 = idx & 15;
            uint32_t so = r * 256 + ((uint32_t)(c16 ^ (r & 7)) << 4);
            CP16(bh + so, &g_wwh[(size_t)r * C_DIM + c16 * 8]);
            CP16(bl + so, &g_wwl[(size_t)r * C_DIM + c16 * 8]);
        }
        CP_COMMIT();
    }

    // mix -> smem (overwrite vals region; all vals reads done)
#pragma unroll
    for (int mf = 0; mf < 2; mf++)
#pragma unroll
        for (int nf = 0; nf < 4; nf++) {
            int r = wr * 32 + mf * 16 + (lane >> 2);
            int c = wc * 32 + nf * 8 + 2 * (lane & 3);
            uint32_t h0, l0, h1, l1;
            split2(res[mf][nf][0], res[mf][nf][1], h0, l0);
            split2(res[mf][nf][2], res[mf][nf][3], h1, l1);
            uint32_t so0 = r * 256 + ((uint32_t)((c >> 3) ^ (r & 7)) << 4) + ((c & 7) << 1);
            uint32_t so1 = (r + 8) * 256 + ((uint32_t)((c >> 3) ^ ((r + 8) & 7)) << 4) + ((c & 7) << 1);
            *(uint32_t*)(sm + VH + so0) = h0;
            *(uint32_t*)(sm + VL + so0) = l0;
            *(uint32_t*)(sm + VH + so1) = h1;
            *(uint32_t*)(sm + VL + so1) = l1;
        }
    __syncthreads();

    // =========================== PHASE 3 ===========================
    {
        const float alpha = __ldg(oscale);
        auto ldB2 = [&](int n0, int s) {
            uint32_t bh = sb + s * 65536;
            uint32_t bl = sb + s * 65536 + 32768;
#pragma unroll
            for (int i = 0; i < 4; i++) {
                int idx = tid + i * 512;
                int r = idx >> 4, c16 = idx & 15;
                uint32_t so = r * 256 + ((uint32_t)(c16 ^ (r & 7)) << 4);
                CP16(bh + so, &g_wwh[(size_t)(n0 + r) * C_DIM + c16 * 8]);
                CP16(bl + so, &g_wwl[(size_t)(n0 + r) * C_DIM + c16 * 8]);
            }
        };

#pragma unroll 1
        for (int nt = 0; nt < 32; nt++) {
            const int s = nt & 1;
            if (nt < 31) { ldB2((nt + 1) * 128, 1 - s); CP_COMMIT(); cp_wait<1>(); }
            else cp_wait<0>();
            __syncthreads();

            float acc[2][4][4];
#pragma unroll
            for (int a = 0; a < 2; a++)
#pragma unroll
                for (int b = 0; b < 4; b++)
#pragma unroll
                    for (int c = 0; c < 4; c++) acc[a][b][c] = 0.0f;

            const uint32_t bh0 = sb + s * 65536;
            const uint32_t bl0 = sb + s * 65536 + 32768;
#pragma unroll
            for (int ks = 0; ks < 8; ks++) {
                uint32_t Ah[2][4], Al[2][4], Bh[4][2], Bl[4][2];
#pragma unroll
                for (int mf = 0; mf < 2; mf++) {
                    uint32_t rr = wr * 32 + mf * 16 + arow16;
                    uint32_t so = rr * 256 + ((uint32_t)((ks * 2 + ako) ^ (rr & 7)) << 4);
                    ldsm4(Ah[mf][0], Ah[mf][1], Ah[mf][2], Ah[mf][3], sb + VH + so);
                    ldsm4(Al[mf][0], Al[mf][1], Al[mf][2], Al[mf][3], sb + VL + so);
                }
#pragma unroll
                for (int p = 0; p < 2; p++) {
                    uint32_t rr = wc * 32 + brow8 + p * 16;
                    uint32_t so = rr * 256 + ((uint32_t)((ks * 2 + bko) ^ (rr & 7)) << 4);
                    ldsm4(Bh[2 * p][0], Bh[2 * p][1], Bh[2 * p + 1][0], Bh[2 * p + 1][1], bh0 + so);
                    ldsm4(Bl[2 * p][0], Bl[2 * p][1], Bl[2 * p + 1][0], Bl[2 * p + 1][1], bl0 + so);
                }
#pragma unroll
                for (int mf = 0; mf < 2; mf++)
#pragma unroll
                    for (int nf = 0; nf < 4; nf++) {
                        mma_bf16(acc[mf][nf], Ah[mf], Bh[nf]);
                        mma_bf16(acc[mf][nf], Ah[mf], Bl[nf]);
                        mma_bf16(acc[mf][nf], Al[mf], Bh[nf]);
                    }
            }
#pragma unroll
            for (int mf = 0; mf < 2; mf++)
#pragma unroll
                for (int nf = 0; nf < 4; nf++) {
                    int r = m0 + wr * 32 + mf * 16 + (lane >> 2);
                    int c = nt * 128 + wc * 32 + nf * 8 + 2 * (lane & 3);
                    float2 v0 = make_float2(acc[mf][nf][0] * alpha, acc[mf][nf][1] * alpha);
                    float2 v1 = make_float2(acc[mf][nf][2] * alpha, acc[mf][nf][3] * alpha);
                    *(float2*)&out[(size_t)r * V_DIM + c] = v0;
                    *(float2*)&out[(size_t)(r + 8) * V_DIM + c] = v1;
                }
            __syncthreads();
        }
    }
}

// ---------------------------------------------------------------------------
extern "C" void kernel_launch(void* const* d_in, const int* in_sizes, int n_in,
                              void* d_out, int out_size)
{
    const float* x      = (const float*)d_in[0];
    const float* basis  = (const float*)d_in[1];
    const float* rcoef  = (const float*)d_in[2];
    const float* wcoef  = (const float*)d_in[3];
    const float* logits = (const float*)d_in[4];
    const float* opW    = (const float*)d_in[5];
    const float* opB    = (const float*)d_in[6];
    const float* oscale = (const float*)d_in[7];
    float* out = (float*)d_out;

    float* p_rw;
    cudaGetSymbolAddress((void**)&p_rw, g_rw);

    static bool attr_done = false;
    if (!attr_done) {
        cudaFuncSetAttribute(mega, cudaFuncAttributeMaxDynamicSharedMemorySize, 196608);
        attr_done = true;
    }

    // 1) addressing scores: z=0 read (fp32), z=1 write (split bf16)
    sgemm_addr<<<dim3(1, V_DIM / 128, 2), 256>>>(basis, rcoef, wcoef);
    // 2) read softmax + transpose + split; op weights transpose + split
    col_softmax_T<<<C_DIM, 256>>>(p_rw);
    prep_wT<<<N_OPS * C_DIM * C_DIM / 256, 256>>>(opW);
    // 3) fused pipeline
    mega<<<M_TOK / 128, 512, 196608>>>(x, logits, opB, out, oscale);
}

// round 12
// speedup vs baseline: 1.1729x; 1.1190x over previous
#include <cuda_runtime.h>
#include <cuda_bf16.h>
#include <math.h>
#include <stdint.h>

#define M_TOK 16384
#define V_DIM 4096
#define C_DIM 128
#define K_NB2 128
#define N_OPS 8

// ------------------------- scratch (device globals) -------------------------
__device__ float g_rw[V_DIM * C_DIM];                  // read scores fp32
__device__ __nv_bfloat16 g_rwTh[C_DIM * V_DIM];        // read_w^T hi (C x V)
__device__ __nv_bfloat16 g_rwTl[C_DIM * V_DIM];
__device__ __nv_bfloat16 g_wwh[V_DIM * C_DIM];         // write_w hi (V x C)
__device__ __nv_bfloat16 g_wwl[V_DIM * C_DIM];
__device__ __nv_bfloat16 g_wTh[N_OPS * C_DIM * C_DIM]; // op W^T [op][n][k]
__device__ __nv_bfloat16 g_wTl[N_OPS * C_DIM * C_DIM];

// ------------------------- helpers -------------------------
__device__ __forceinline__ uint32_t smem_u32(const void* p) {
    uint32_t a;
    asm("{ .reg .u64 t; cvta.to.shared.u64 t, %1; cvt.u32.u64 %0, t; }" : "=r"(a) : "l"(p));
    return a;
}
#define CP16(saddr, gptr) \
    asm volatile("cp.async.cg.shared.global [%0], [%1], 16;" :: "r"(saddr), "l"(gptr) : "memory")
#define CP_COMMIT() asm volatile("cp.async.commit_group;" ::: "memory")
template <int N> __device__ __forceinline__ void cp_wait() {
    asm volatile("cp.async.wait_group %0;" :: "n"(N) : "memory");
}
__device__ __forceinline__ void ldsm4(uint32_t& r0, uint32_t& r1, uint32_t& r2, uint32_t& r3, uint32_t a) {
    asm volatile("ldmatrix.sync.aligned.m8n8.x4.shared.b16 {%0,%1,%2,%3}, [%4];"
        : "=r"(r0), "=r"(r1), "=r"(r2), "=r"(r3) : "r"(a));
}
__device__ __forceinline__ void mma_bf16(float c[4], const uint32_t a[4], const uint32_t b[2]) {
    asm volatile(
        "mma.sync.aligned.m16n8k16.row.col.f32.bf16.bf16.f32 "
        "{%0,%1,%2,%3},{%4,%5,%6,%7},{%8,%9},{%0,%1,%2,%3};"
        : "+f"(c[0]), "+f"(c[1]), "+f"(c[2]), "+f"(c[3])
        : "r"(a[0]), "r"(a[1]), "r"(a[2]), "r"(a[3]), "r"(b[0]), "r"(b[1]));
}
__device__ __forceinline__ void split2(float a, float b, uint32_t& hi, uint32_t& lo) {
    __nv_bfloat16 ha = __float2bfloat16(a), hb = __float2bfloat16(b);
    __nv_bfloat16 la = __float2bfloat16(a - __bfloat162float(ha));
    __nv_bfloat16 lb = __float2bfloat16(b - __bfloat162float(hb));
    hi = (uint32_t)__bfloat16_as_ushort(ha) | ((uint32_t)__bfloat16_as_ushort(hb) << 16);
    lo = (uint32_t)__bfloat16_as_ushort(la) | ((uint32_t)__bfloat16_as_ushort(lb) << 16);
}
__device__ __forceinline__ void split1(float a, uint16_t& h, uint16_t& l) {
    __nv_bfloat16 ha = __float2bfloat16(a);
    __nv_bfloat16 la = __float2bfloat16(a - __bfloat162float(ha));
    h = __bfloat16_as_ushort(ha);
    l = __bfloat16_as_ushort(la);
}

// ---------------------------------------------------------------------------
// Addressing GEMM: scores = basis(4096x128) @ coeff(128x128)^T
// z=0: rcoef -> g_rw fp32;  z=1: wcoef -> split to g_wwh/g_wwl
// ---------------------------------------------------------------------------
__global__ __launch_bounds__(256) void sgemm_addr(
    const float* __restrict__ A, const float* __restrict__ B0,
    const float* __restrict__ B1)
{
    __shared__ float As[16][128];
    __shared__ float Bs[16][128];
    const int tid = threadIdx.x;
    const int tc = tid % 16, tr = tid / 16;
    const int m0 = blockIdx.y * 128;
    const int path = blockIdx.z;
    const float* B = path ? B1 : B0;

    float acc[8][8];
#pragma unroll
    for (int i = 0; i < 8; i++)
#pragma unroll
        for (int j = 0; j < 8; j++) acc[i][j] = 0.0f;

    for (int k0 = 0; k0 < K_NB2; k0 += 16) {
#pragma unroll
        for (int i = 0; i < 2; i++) {
            int idx = tid + i * 256;
            int row = idx / 4, c4 = idx % 4;
            float4 va = *(const float4*)&A[(size_t)(m0 + row) * K_NB2 + k0 + c4 * 4];
            As[c4 * 4 + 0][row] = va.x; As[c4 * 4 + 1][row] = va.y;
            As[c4 * 4 + 2][row] = va.z; As[c4 * 4 + 3][row] = va.w;
            float4 vb = *(const float4*)&B[(size_t)row * K_NB2 + k0 + c4 * 4];
            Bs[c4 * 4 + 0][row] = vb.x; Bs[c4 * 4 + 1][row] = vb.y;
            Bs[c4 * 4 + 2][row] = vb.z; Bs[c4 * 4 + 3][row] = vb.w;
        }
        __syncthreads();
#pragma unroll
        for (int k = 0; k < 16; k++) {
            float ra[8], rb[8];
#pragma unroll
            for (int i = 0; i < 8; i++) ra[i] = As[k][tr * 8 + i];
#pragma unroll
            for (int j = 0; j < 8; j++) rb[j] = Bs[k][tc * 8 + j];
#pragma unroll
            for (int i = 0; i < 8; i++)
#pragma unroll
                for (int j = 0; j < 8; j++) acc[i][j] += ra[i] * rb[j];
        }
        __syncthreads();
    }
#pragma unroll
    for (int i = 0; i < 8; i++) {
        const size_t base = (size_t)(m0 + tr * 8 + i) * C_DIM + tc * 8;
        if (path == 0) {
#pragma unroll
            for (int j = 0; j < 8; j++) g_rw[base + j] = acc[i][j];
        } else {
#pragma unroll
            for (int j = 0; j < 8; j++) {
                uint16_t h, l;
                split1(acc[i][j], h, l);
                g_wwh[base + j] = __ushort_as_bfloat16(h);
                g_wwl[base + j] = __ushort_as_bfloat16(l);
            }
        }
    }
}

// ---------------------------------------------------------------------------
// Column softmax over V (axis 0); write transposed bf16 hi/lo (C x V)
// ---------------------------------------------------------------------------
__global__ __launch_bounds__(256) void col_softmax_T(const float* __restrict__ S)
{
    __shared__ float col[V_DIM];
    __shared__ float red[256];
    const int c = blockIdx.x;
    const int tid = threadIdx.x;

    float m = -1e30f;
    for (int v = tid; v < V_DIM; v += 256) {
        float x = S[(size_t)v * C_DIM + c];
        col[v] = x;
        m = fmaxf(m, x);
    }
    red[tid] = m; __syncthreads();
    for (int s = 128; s > 0; s >>= 1) { if (tid < s) red[tid] = fmaxf(red[tid], red[tid + s]); __syncthreads(); }
    m = red[0]; __syncthreads();

    float sum = 0.0f;
    for (int v = tid; v < V_DIM; v += 256) { float e = expf(col[v] - m); col[v] = e; sum += e; }
    red[tid] = sum; __syncthreads();
    for (int s = 128; s > 0; s >>= 1) { if (tid < s) red[tid] += red[tid + s]; __syncthreads(); }
    const float inv = 1.0f / red[0];

    for (int v = tid; v < V_DIM; v += 256) {
        uint16_t h, l;
        split1(col[v] * inv, h, l);
        g_rwTh[(size_t)c * V_DIM + v] = __ushort_as_bfloat16(h);
        g_rwTl[(size_t)c * V_DIM + v] = __ushort_as_bfloat16(l);
    }
}

__global__ __launch_bounds__(256) void prep_wT(const float* __restrict__ W)
{
    int idx = blockIdx.x * 256 + threadIdx.x;
    int op = idx >> 14;
    int rem = idx & 16383;
    int n = rem >> 7, k = rem & 127;
    uint16_t h, l;
    split1(W[op * 16384 + k * 128 + n], h, l);
    g_wTh[idx] = __ushort_as_bfloat16(h);
    g_wTl[idx] = __ushort_as_bfloat16(l);
}

// ---------------------------------------------------------------------------
// MEGA kernel, 512 threads (16 warps, 4x4 warp grid, warp tile 32x32).
//   phase1: values = x @ read_w        (K=4096, 3-stage pipelined)
//   phase2: mix = sum_i w_i f_i(values @ W_i + b_i)
//   phase3: out = mix @ write_w^T * out_scale
// Dynamic smem 192KB:
//   phase1: A stages i*32K (i=0..2, hi/lo 16K each) | B stages 96K+i*32K
//   phase2/3: W / write_w stages s*64K (hi/lo 32K each), s=0..1
//   vals/mix: hi at 128K, lo at 160K (256B rows, swizzled)
// ---------------------------------------------------------------------------
__global__ __launch_bounds__(512, 1) void mega(
    const float* __restrict__ x, const float* __restrict__ logits,
    const float* __restrict__ bias, float* __restrict__ out,
    const float* __restrict__ oscale)
{
    extern __shared__ char sm[];
    __shared__ float bs[N_OPS * C_DIM];
    const uint32_t sb = smem_u32(sm);
    const int tid = threadIdx.x, lane = tid & 31, wid = tid >> 5;
    const int wr = wid & 3, wc = wid >> 2;          // 4x4 warps, warp tile 32x32
    const int m0 = blockIdx.x * 128;
    const float* xbase = x + (size_t)m0 * V_DIM;

    const uint32_t VH = 131072, VL = 163840;

    // bias + logit softmax
#pragma unroll
    for (int i = 0; i < 2; i++) bs[tid + i * 512] = bias[tid + i * 512];
    float wv[N_OPS];
    float mx = -1e30f;
#pragma unroll
    for (int i = 0; i < N_OPS; i++) { wv[i] = __ldg(&logits[i]); mx = fmaxf(mx, wv[i]); }
    float sumw = 0.0f;
#pragma unroll
    for (int i = 0; i < N_OPS; i++) { wv[i] = expf(wv[i] - mx); sumw += wv[i]; }
#pragma unroll
    for (int i = 0; i < N_OPS; i++) wv[i] /= sumw;

    // fragment index helpers
    const int arow16 = lane & 15;
    const int ako = lane >> 4;
    const int brow8 = ((lane >> 4) & 1) * 8 + (lane & 7);
    const int bko = (lane >> 3) & 1;

    // =========================== PHASE 1 ===========================
    {
        float4 apf[4];
        float acc[2][4][4];
#pragma unroll
        for (int a = 0; a < 2; a++)
#pragma unroll
            for (int b = 0; b < 4; b++)
#pragma unroll
                for (int c = 0; c < 4; c++) acc[a][b][c] = 0.0f;

        auto ldA = [&](int k0) {
#pragma unroll
            for (int i = 0; i < 4; i++) {
                int idx = tid + i * 512;
                apf[i] = *(const float4*)&xbase[(size_t)(idx >> 4) * V_DIM + k0 + (idx & 15) * 4];
            }
        };
        auto stA = [&](int st) {
            char* ah = sm + st * 32768;
            char* al = sm + st * 32768 + 16384;
#pragma unroll
            for (int i = 0; i < 4; i++) {
                int idx = tid + i * 512;
                int r = idx >> 4, c4 = idx & 15;
                uint32_t h0, l0, h1, l1;
                split2(apf[i].x, apf[i].y, h0, l0);
                split2(apf[i].z, apf[i].w, h1, l1);
                uint32_t so = r * 128 + ((uint32_t)((c4 >> 1) ^ (r & 7)) << 4) + (c4 & 1) * 8;
                *(uint2*)(ah + so) = make_uint2(h0, h1);
                *(uint2*)(al + so) = make_uint2(l0, l1);
            }
        };
        auto ldB = [&](int k0, int st) {
            uint32_t bh = sb + 98304 + st * 32768;
            uint32_t bl = bh + 16384;
#pragma unroll
            for (int i = 0; i < 2; i++) {
                int idx = tid + i * 512;
                int r = idx >> 3, c = idx & 7;
                uint32_t so = r * 128 + ((uint32_t)(c ^ (r & 7)) << 4);
                CP16(bh + so, &g_rwTh[(size_t)r * V_DIM + k0 + c * 8]);
                CP16(bl + so, &g_rwTl[(size_t)r * V_DIM + k0 + c * 8]);
            }
        };

        // prologue: fill stage0 (A+B), stage1 (B), regs hold chunk1
        ldA(0);
        ldB(0, 0); CP_COMMIT();
        stA(0);
        ldA(64);
        ldB(64, 1); CP_COMMIT();

        int stc = 0, stn = 1, stn2 = 2;
        for (int ch = 0; ch < 64; ch++) {
            if (ch < 63) stA(stn);                       // store chunk ch+1 (one ahead)
            if (ch < 62) ldA((ch + 2) * 64);             // regs two ahead
            if (ch < 63) cp_wait<1>(); else cp_wait<0>();  // B(ch) landed
            __syncthreads();
            if (ch < 62) { ldB((ch + 2) * 64, stn2); CP_COMMIT(); }  // post-sync: stage stn2 free

            const uint32_t ah0 = sb + stc * 32768;
            const uint32_t al0 = ah0 + 16384;
            const uint32_t bh0 = sb + 98304 + stc * 32768;
            const uint32_t bl0 = bh0 + 16384;
#pragma unroll
            for (int ks = 0; ks < 4; ks++) {
                uint32_t Ah[2][4], Al[2][4], Bh[4][2], Bl[4][2];
#pragma unroll
                for (int mf = 0; mf < 2; mf++) {
                    uint32_t rr = wr * 32 + mf * 16 + arow16;
                    uint32_t so = rr * 128 + ((uint32_t)((ks * 2 + ako) ^ (rr & 7)) << 4);
                    ldsm4(Ah[mf][0], Ah[mf][1], Ah[mf][2], Ah[mf][3], ah0 + so);
                    ldsm4(Al[mf][0], Al[mf][1], Al[mf][2], Al[mf][3], al0 + so);
                }
#pragma unroll
                for (int p = 0; p < 2; p++) {
                    uint32_t rr = wc * 32 + brow8 + p * 16;
                    uint32_t so = rr * 128 + ((uint32_t)((ks * 2 + bko) ^ (rr & 7)) << 4);
                    ldsm4(Bh[2 * p][0], Bh[2 * p][1], Bh[2 * p + 1][0], Bh[2 * p + 1][1], bh0 + so);
                    ldsm4(Bl[2 * p][0], Bl[2 * p][1], Bl[2 * p + 1][0], Bl[2 * p + 1][1], bl0 + so);
                }
#pragma unroll
                for (int mf = 0; mf < 2; mf++)
#pragma unroll
                    for (int nf = 0; nf < 4; nf++) {
                        mma_bf16(acc[mf][nf], Ah[mf], Bh[nf]);
                        mma_bf16(acc[mf][nf], Ah[mf], Bl[nf]);
                        mma_bf16(acc[mf][nf], Al[mf], Bh[nf]);
                    }
            }
            int t = stc; stc = stn; stn = stn2; stn2 = t;
        }

        // vals -> smem (bf16 hi/lo, 256B swizzled rows) — regions = old B stages
        // 1&2; last MMA reads B stage 0 and A stage 0, so no conflict.
#pragma unroll
        for (int mf = 0; mf < 2; mf++)
#pragma unroll
            for (int nf = 0; nf < 4; nf++) {
                int r = wr * 32 + mf * 16 + (lane >> 2);
                int c = wc * 32 + nf * 8 + 2 * (lane & 3);
                uint32_t h0, l0, h1, l1;
                split2(acc[mf][nf][0], acc[mf][nf][1], h0, l0);
                split2(acc[mf][nf][2], acc[mf][nf][3], h1, l1);
                uint32_t so0 = r * 256 + ((uint32_t)((c >> 3) ^ (r & 7)) << 4) + ((c & 7) << 1);
                uint32_t so1 = (r + 8) * 256 + ((uint32_t)((c >> 3) ^ ((r + 8) & 7)) << 4) + ((c & 7) << 1);
                *(uint32_t*)(sm + VH + so0) = h0;
                *(uint32_t*)(sm + VL + so0) = l0;
                *(uint32_t*)(sm + VH + so1) = h1;
                *(uint32_t*)(sm + VL + so1) = l1;
            }
        __syncthreads();
    }

    // =========================== PHASE 2 ===========================
    float res[2][4][4];
#pragma unroll
    for (int a = 0; a < 2; a++)
#pragma unroll
        for (int b = 0; b < 4; b++)
#pragma unroll
            for (int c = 0; c < 4; c++) res[a][b][c] = 0.0f;

    {
        auto ldW = [&](int op, int s) {
            uint32_t wh = sb + s * 65536;
            uint32_t wl = wh + 32768;
#pragma unroll
            for (int i = 0; i < 4; i++) {
                int idx = tid + i * 512;
                int r = idx >> 4, c16 = idx & 15;
                uint32_t so = r * 256 + ((uint32_t)(c16 ^ (r & 7)) << 4);
                CP16(wh + so, &g_wTh[(size_t)op * 16384 + r * C_DIM + c16 * 8]);
                CP16(wl + so, &g_wTl[(size_t)op * 16384 + r * C_DIM + c16 * 8]);
            }
        };
        auto ldWW = [&](int n0, int s) {   // write_w tile (phase3 prefetch)
            uint32_t bh = sb + s * 65536;
            uint32_t bl = bh + 32768;
#pragma unroll
            for (int i = 0; i < 4; i++) {
                int idx = tid + i * 512;
                int r = idx >> 4, c16 = idx & 15;
                uint32_t so = r * 256 + ((uint32_t)(c16 ^ (r & 7)) << 4);
                CP16(bh + so, &g_wwh[(size_t)(n0 + r) * C_DIM + c16 * 8]);
                CP16(bl + so, &g_wwl[(size_t)(n0 + r) * C_DIM + c16 * 8]);
            }
        };

        ldW(0, 0); CP_COMMIT();   // exposed once (~L2 latency)

#pragma unroll 1
        for (int op = 0; op < N_OPS; op++) {
            const int s = op & 1;
            cp_wait<0>();
            __syncthreads();
            if (op < 7) { ldW(op + 1, 1 - s); CP_COMMIT(); }
            else        { ldWW(0, 0); CP_COMMIT(); }   // phase3 tile0 into stage0

            float acc[2][4][4];
#pragma unroll
            for (int a = 0; a < 2; a++)
#pragma unroll
                for (int b = 0; b < 4; b++)
#pragma unroll
                    for (int c = 0; c < 4; c++) acc[a][b][c] = 0.0f;

            const uint32_t wh0 = sb + s * 65536;
            const uint32_t wl0 = wh0 + 32768;
#pragma unroll
            for (int ks = 0; ks < 8; ks++) {
                uint32_t Ah[2][4], Al[2][4], Bh[4][2], Bl[4][2];
#pragma unroll
                for (int mf = 0; mf < 2; mf++) {
                    uint32_t rr = wr * 32 + mf * 16 + arow16;
                    uint32_t so = rr * 256 + ((uint32_t)((ks * 2 + ako) ^ (rr & 7)) << 4);
                    ldsm4(Ah[mf][0], Ah[mf][1], Ah[mf][2], Ah[mf][3], sb + VH + so);
                    ldsm4(Al[mf][0], Al[mf][1], Al[mf][2], Al[mf][3], sb + VL + so);
                }
#pragma unroll
                for (int p = 0; p < 2; p++) {
                    uint32_t rr = wc * 32 + brow8 + p * 16;
                    uint32_t so = rr * 256 + ((uint32_t)((ks * 2 + bko) ^ (rr & 7)) << 4);
                    ldsm4(Bh[2 * p][0], Bh[2 * p][1], Bh[2 * p + 1][0], Bh[2 * p + 1][1], wh0 + so);
                    ldsm4(Bl[2 * p][0], Bl[2 * p][1], Bl[2 * p + 1][0], Bl[2 * p + 1][1], wl0 + so);
                }
#pragma unroll
                for (int mf = 0; mf < 2; mf++)
#pragma unroll
                    for (int nf = 0; nf < 4; nf++) {
                        mma_bf16(acc[mf][nf], Ah[mf], Bh[nf]);
                        mma_bf16(acc[mf][nf], Ah[mf], Bl[nf]);
                        mma_bf16(acc[mf][nf], Al[mf], Bh[nf]);
                    }
            }
            const float w = wv[op];
#pragma unroll
            for (int mf = 0; mf < 2; mf++)
#pragma unroll
                for (int nf = 0; nf < 4; nf++)
#pragma unroll
                    for (int j = 0; j < 4; j++) {
                        int col = wc * 32 + nf * 8 + 2 * (lane & 3) + (j & 1);
                        float v = acc[mf][nf][j] + bs[op * C_DIM + col];
                        float f;
                        switch (op) {
                            case 0: f = v; break;
                            case 1: f = fmaxf(v, 0.0f); break;
                            case 2: f = 0.5f * v * (1.0f + erff(v * 0.70710678118654752f)); break;
                            case 3: f = v * v; break;
                            case 4: f = -v; break;
                            case 5: f = fabsf(v); break;
                            case 6: f = tanhf(v); break;
                            default: f = 1.0f / (1.0f + expf(-v)); break;
                        }
                        res[mf][nf][j] += w * f;
                    }
        }
    }

    // all warps done reading vals before overwriting with mix
    __syncthreads();
#pragma unroll
    for (int mf = 0; mf < 2; mf++)
#pragma unroll
        for (int nf = 0; nf < 4; nf++) {
            int r = wr * 32 + mf * 16 + (lane >> 2);
            int c = wc * 32 + nf * 8 + 2 * (lane & 3);
            uint32_t h0, l0, h1, l1;
            split2(res[mf][nf][0], res[mf][nf][1], h0, l0);
            split2(res[mf][nf][2], res[mf][nf][3], h1, l1);
            uint32_t so0 = r * 256 + ((uint32_t)((c >> 3) ^ (r & 7)) << 4) + ((c & 7) << 1);
            uint32_t so1 = (r + 8) * 256 + ((uint32_t)((c >> 3) ^ ((r + 8) & 7)) << 4) + ((c & 7) << 1);
            *(uint32_t*)(sm + VH + so0) = h0;
            *(uint32_t*)(sm + VL + so0) = l0;
            *(uint32_t*)(sm + VH + so1) = h1;
            *(uint32_t*)(sm + VL + so1) = l1;
        }
    __syncthreads();

    // =========================== PHASE 3 ===========================
    {
        const float alpha = __ldg(oscale);
        auto ldB2 = [&](int n0, int s) {
            uint32_t bh = sb + s * 65536;
            uint32_t bl = bh + 32768;
#pragma unroll
            for (int i = 0; i < 4; i++) {
                int idx = tid + i * 512;
                int r = idx >> 4, c16 = idx & 15;
                uint32_t so = r * 256 + ((uint32_t)(c16 ^ (r & 7)) << 4);
                CP16(bh + so, &g_wwh[(size_t)(n0 + r) * C_DIM + c16 * 8]);
                CP16(bl + so, &g_wwl[(size_t)(n0 + r) * C_DIM + c16 * 8]);
            }
        };

#pragma unroll 1
        for (int nt = 0; nt < 32; nt++) {
            const int s = nt & 1;
            cp_wait<0>();
            __syncthreads();
            if (nt < 31) { ldB2((nt + 1) * 128, 1 - s); CP_COMMIT(); }

            float acc[2][4][4];
#pragma unroll
            for (int a = 0; a < 2; a++)
#pragma unroll
                for (int b = 0; b < 4; b++)
#pragma unroll
                    for (int c = 0; c < 4; c++) acc[a][b][c] = 0.0f;

            const uint32_t bh0 = sb + s * 65536;
            const uint32_t bl0 = bh0 + 32768;
#pragma unroll
            for (int ks = 0; ks < 8; ks++) {
                uint32_t Ah[2][4], Al[2][4], Bh[4][2], Bl[4][2];
#pragma unroll
                for (int mf = 0; mf < 2; mf++) {
                    uint32_t rr = wr * 32 + mf * 16 + arow16;
                    uint32_t so = rr * 256 + ((uint32_t)((ks * 2 + ako) ^ (rr & 7)) << 4);
                    ldsm4(Ah[mf][0], Ah[mf][1], Ah[mf][2], Ah[mf][3], sb + VH + so);
                    ldsm4(Al[mf][0], Al[mf][1], Al[mf][2], Al[mf][3], sb + VL + so);
                }
#pragma unroll
                for (int p = 0; p < 2; p++) {
                    uint32_t rr = wc * 32 + brow8 + p * 16;
                    uint32_t so = rr * 256 + ((uint32_t)((ks * 2 + bko) ^ (rr & 7)) << 4);
                    ldsm4(Bh[2 * p][0], Bh[2 * p][1], Bh[2 * p + 1][0], Bh[2 * p + 1][1], bh0 + so);
                    ldsm4(Bl[2 * p][0], Bl[2 * p][1], Bl[2 * p + 1][0], Bl[2 * p + 1][1], bl0 + so);
                }
#pragma unroll
                for (int mf = 0; mf < 2; mf++)
#pragma unroll
                    for (int nf = 0; nf < 4; nf++) {
                        mma_bf16(acc[mf][nf], Ah[mf], Bh[nf]);
                        mma_bf16(acc[mf][nf], Ah[mf], Bl[nf]);
                        mma_bf16(acc[mf][nf], Al[mf], Bh[nf]);
                    }
            }
#pragma unroll
            for (int mf = 0; mf < 2; mf++)
#pragma unroll
                for (int nf = 0; nf < 4; nf++) {
                    int r = m0 + wr * 32 + mf * 16 + (lane >> 2);
                    int c = nt * 128 + wc * 32 + nf * 8 + 2 * (lane & 3);
                    float2 v0 = make_float2(acc[mf][nf][0] * alpha, acc[mf][nf][1] * alpha);
                    float2 v1 = make_float2(acc[mf][nf][2] * alpha, acc[mf][nf][3] * alpha);
                    *(float2*)&out[(size_t)r * V_DIM + c] = v0;
                    *(float2*)&out[(size_t)(r + 8) * V_DIM + c] = v1;
                }
        }
    }
}

// ---------------------------------------------------------------------------
extern "C" void kernel_launch(void* const* d_in, const int* in_sizes, int n_in,
                              void* d_out, int out_size)
{
    const float* x      = (const float*)d_in[0];
    const float* basis  = (const float*)d_in[1];
    const float* rcoef  = (const float*)d_in[2];
    const float* wcoef  = (const float*)d_in[3];
    const float* logits = (const float*)d_in[4];
    const float* opW    = (const float*)d_in[5];
    const float* opB    = (const float*)d_in[6];
    const float* oscale = (const float*)d_in[7];
    float* out = (float*)d_out;

    float* p_rw;
    cudaGetSymbolAddress((void**)&p_rw, g_rw);

    static bool attr_done = false;
    if (!attr_done) {
        cudaFuncSetAttribute(mega, cudaFuncAttributeMaxDynamicSharedMemorySize, 196608);
        attr_done = true;
    }

    // 1) addressing scores: z=0 read (fp32), z=1 write (split bf16)
    sgemm_addr<<<dim3(1, V_DIM / 128, 2), 256>>>(basis, rcoef, wcoef);
    // 2) read softmax + transpose + split; op weights transpose + split
    col_softmax_T<<<C_DIM, 256>>>(p_rw);
    prep_wT<<<N_OPS * C_DIM * C_DIM / 256, 256>>>(opW);
    // 3) fused pipeline
    mega<<<M_TOK / 128, 512, 196608>>>(x, logits, opB, out, oscale);
}

// round 13
// speedup vs baseline: 1.1730x; 1.0001x over previous
#include <cuda_runtime.h>
#include <cuda_bf16.h>
#include <math.h>
#include <stdint.h>

#define M_TOK 16384
#define V_DIM 4096
#define C_DIM 128
#define K_NB2 128
#define N_OPS 8
#define MT 64          // M rows per CTA

// ------------------------- scratch (device globals) -------------------------
__device__ float g_rw[V_DIM * C_DIM];                  // read scores fp32
__device__ __nv_bfloat16 g_rwTh[C_DIM * V_DIM];        // read_w^T hi (C x V)
__device__ __nv_bfloat16 g_rwTl[C_DIM * V_DIM];
__device__ __nv_bfloat16 g_wwh[V_DIM * C_DIM];         // write_w hi (V x C)
__device__ __nv_bfloat16 g_wwl[V_DIM * C_DIM];
__device__ __nv_bfloat16 g_wTh[N_OPS * C_DIM * C_DIM]; // op W^T [op][n][k]
__device__ __nv_bfloat16 g_wTl[N_OPS * C_DIM * C_DIM];

// ------------------------- helpers -------------------------
__device__ __forceinline__ uint32_t smem_u32(const void* p) {
    uint32_t a;
    asm("{ .reg .u64 t; cvta.to.shared.u64 t, %1; cvt.u32.u64 %0, t; }" : "=r"(a) : "l"(p));
    return a;
}
#define CP16(saddr, gptr) \
    asm volatile("cp.async.cg.shared.global [%0], [%1], 16;" :: "r"(saddr), "l"(gptr) : "memory")
#define CP_COMMIT() asm volatile("cp.async.commit_group;" ::: "memory")
template <int N> __device__ __forceinline__ void cp_wait() {
    asm volatile("cp.async.wait_group %0;" :: "n"(N) : "memory");
}
__device__ __forceinline__ void ldsm4(uint32_t& r0, uint32_t& r1, uint32_t& r2, uint32_t& r3, uint32_t a) {
    asm volatile("ldmatrix.sync.aligned.m8n8.x4.shared.b16 {%0,%1,%2,%3}, [%4];"
        : "=r"(r0), "=r"(r1), "=r"(r2), "=r"(r3) : "r"(a));
}
__device__ __forceinline__ void mma_bf16(float c[4], const uint32_t a[4], const uint32_t b[2]) {
    asm volatile(
        "mma.sync.aligned.m16n8k16.row.col.f32.bf16.bf16.f32 "
        "{%0,%1,%2,%3},{%4,%5,%6,%7},{%8,%9},{%0,%1,%2,%3};"
        : "+f"(c[0]), "+f"(c[1]), "+f"(c[2]), "+f"(c[3])
        : "r"(a[0]), "r"(a[1]), "r"(a[2]), "r"(a[3]), "r"(b[0]), "r"(b[1]));
}
__device__ __forceinline__ void split2(float a, float b, uint32_t& hi, uint32_t& lo) {
    __nv_bfloat16 ha = __float2bfloat16(a), hb = __float2bfloat16(b);
    __nv_bfloat16 la = __float2bfloat16(a - __bfloat162float(ha));
    __nv_bfloat16 lb = __float2bfloat16(b - __bfloat162float(hb));
    hi = (uint32_t)__bfloat16_as_ushort(ha) | ((uint32_t)__bfloat16_as_ushort(hb) << 16);
    lo = (uint32_t)__bfloat16_as_ushort(la) | ((uint32_t)__bfloat16_as_ushort(lb) << 16);
}
__device__ __forceinline__ void split1(float a, uint16_t& h, uint16_t& l) {
    __nv_bfloat16 ha = __float2bfloat16(a);
    __nv_bfloat16 la = __float2bfloat16(a - __bfloat162float(ha));
    h = __bfloat16_as_ushort(ha);
    l = __bfloat16_as_ushort(la);
}

// ---------------------------------------------------------------------------
// Addressing GEMM: scores = basis(4096x128) @ coeff(128x128)^T
// ---------------------------------------------------------------------------
__global__ __launch_bounds__(256) void sgemm_addr(
    const float* __restrict__ A, const float* __restrict__ B0,
    const float* __restrict__ B1)
{
    __shared__ float As[16][128];
    __shared__ float Bs[16][128];
    const int tid = threadIdx.x;
    const int tc = tid % 16, tr = tid / 16;
    const int m0 = blockIdx.y * 128;
    const int path = blockIdx.z;
    const float* B = path ? B1 : B0;

    float acc[8][8];
#pragma unroll
    for (int i = 0; i < 8; i++)
#pragma unroll
        for (int j = 0; j < 8; j++) acc[i][j] = 0.0f;

    for (int k0 = 0; k0 < K_NB2; k0 += 16) {
#pragma unroll
        for (int i = 0; i < 2; i++) {
            int idx = tid + i * 256;
            int row = idx / 4, c4 = idx % 4;
            float4 va = *(const float4*)&A[(size_t)(m0 + row) * K_NB2 + k0 + c4 * 4];
            As[c4 * 4 + 0][row] = va.x; As[c4 * 4 + 1][row] = va.y;
            As[c4 * 4 + 2][row] = va.z; As[c4 * 4 + 3][row] = va.w;
            float4 vb = *(const float4*)&B[(size_t)row * K_NB2 + k0 + c4 * 4];
            Bs[c4 * 4 + 0][row] = vb.x; Bs[c4 * 4 + 1][row] = vb.y;
            Bs[c4 * 4 + 2][row] = vb.z; Bs[c4 * 4 + 3][row] = vb.w;
        }
        __syncthreads();
#pragma unroll
        for (int k = 0; k < 16; k++) {
            float ra[8], rb[8];
#pragma unroll
            for (int i = 0; i < 8; i++) ra[i] = As[k][tr * 8 + i];
#pragma unroll
            for (int j = 0; j < 8; j++) rb[j] = Bs[k][tc * 8 + j];
#pragma unroll
            for (int i = 0; i < 8; i++)
#pragma unroll
                for (int j = 0; j < 8; j++) acc[i][j] += ra[i] * rb[j];
        }
        __syncthreads();
    }
#pragma unroll
    for (int i = 0; i < 8; i++) {
        const size_t base = (size_t)(m0 + tr * 8 + i) * C_DIM + tc * 8;
        if (path == 0) {
#pragma unroll
            for (int j = 0; j < 8; j++) g_rw[base + j] = acc[i][j];
        } else {
#pragma unroll
            for (int j = 0; j < 8; j++) {
                uint16_t h, l;
                split1(acc[i][j], h, l);
                g_wwh[base + j] = __ushort_as_bfloat16(h);
                g_wwl[base + j] = __ushort_as_bfloat16(l);
            }
        }
    }
}

// ---------------------------------------------------------------------------
// Column softmax over V (axis 0); write transposed bf16 hi/lo (C x V)
// ---------------------------------------------------------------------------
__global__ __launch_bounds__(256) void col_softmax_T(const float* __restrict__ S)
{
    __shared__ float col[V_DIM];
    __shared__ float red[256];
    const int c = blockIdx.x;
    const int tid = threadIdx.x;

    float m = -1e30f;
    for (int v = tid; v < V_DIM; v += 256) {
        float x = S[(size_t)v * C_DIM + c];
        col[v] = x;
        m = fmaxf(m, x);
    }
    red[tid] = m; __syncthreads();
    for (int s = 128; s > 0; s >>= 1) { if (tid < s) red[tid] = fmaxf(red[tid], red[tid + s]); __syncthreads(); }
    m = red[0]; __syncthreads();

    float sum = 0.0f;
    for (int v = tid; v < V_DIM; v += 256) { float e = expf(col[v] - m); col[v] = e; sum += e; }
    red[tid] = sum; __syncthreads();
    for (int s = 128; s > 0; s >>= 1) { if (tid < s) red[tid] += red[tid + s]; __syncthreads(); }
    const float inv = 1.0f / red[0];

    for (int v = tid; v < V_DIM; v += 256) {
        uint16_t h, l;
        split1(col[v] * inv, h, l);
        g_rwTh[(size_t)c * V_DIM + v] = __ushort_as_bfloat16(h);
        g_rwTl[(size_t)c * V_DIM + v] = __ushort_as_bfloat16(l);
    }
}

__global__ __launch_bounds__(256) void prep_wT(const float* __restrict__ W)
{
    int idx = blockIdx.x * 256 + threadIdx.x;
    int op = idx >> 14;
    int rem = idx & 16383;
    int n = rem >> 7, k = rem & 127;
    uint16_t h, l;
    split1(W[op * 16384 + k * 128 + n], h, l);
    g_wTh[idx] = __ushort_as_bfloat16(h);
    g_wTl[idx] = __ushort_as_bfloat16(l);
}

// ---------------------------------------------------------------------------
// MEGA kernel, 256 threads (8 warps), 64-row M-tile, 2 CTAs/SM.
// Dynamic smem 96KB:
//   phase1: A stages st*16K (hi 8K, lo 8K) | B stages 32K+st*32K (hi 16K, lo 16K)
//   phase2: W k-chunk stages st*32K           | vals at 64K (hi 16K) / 80K (lo)
//   phase3: write_w 64-row n-tiles st*32K     | mix  at 64K / 80K
// ---------------------------------------------------------------------------
__global__ __launch_bounds__(256, 2) void mega(
    const float* __restrict__ x, const float* __restrict__ logits,
    const float* __restrict__ bias, float* __restrict__ out,
    const float* __restrict__ oscale)
{
    extern __shared__ char sm[];
    __shared__ float bs[N_OPS * C_DIM];
    const uint32_t sb = smem_u32(sm);
    const int tid = threadIdx.x, lane = tid & 31, wid = tid >> 5;
    const int wr = wid >> 2, wc = wid & 3;     // 2x4 warps, tile 32x32 (ph1/2)
    const int m0 = blockIdx.x * MT;
    const float* xbase = x + (size_t)m0 * V_DIM;

    const uint32_t VH = 65536, VL = 81920;

    // bias + logit softmax
#pragma unroll
    for (int i = 0; i < 4; i++) bs[tid + i * 256] = bias[tid + i * 256];
    float wv[N_OPS];
    float mx = -1e30f;
#pragma unroll
    for (int i = 0; i < N_OPS; i++) { wv[i] = __ldg(&logits[i]); mx = fmaxf(mx, wv[i]); }
    float sumw = 0.0f;
#pragma unroll
    for (int i = 0; i < N_OPS; i++) { wv[i] = expf(wv[i] - mx); sumw += wv[i]; }
#pragma unroll
    for (int i = 0; i < N_OPS; i++) wv[i] /= sumw;

    const int arow16 = lane & 15;
    const int ako = lane >> 4;
    const int brow8 = ((lane >> 4) & 1) * 8 + (lane & 7);
    const int bko = (lane >> 3) & 1;

    // =========================== PHASE 1 ===========================
    // values(64x128) = x(64x4096) @ read_w(4096x128), BK=64, 2-stage
    {
        float4 apf[4];
        float acc[2][4][4];
#pragma unroll
        for (int a = 0; a < 2; a++)
#pragma unroll
            for (int b = 0; b < 4; b++)
#pragma unroll
                for (int c = 0; c < 4; c++) acc[a][b][c] = 0.0f;

        auto ldA = [&](int k0) {
#pragma unroll
            for (int i = 0; i < 4; i++) {
                int idx = tid + i * 256;
                apf[i] = *(const float4*)&xbase[(size_t)(idx >> 4) * V_DIM + k0 + (idx & 15) * 4];
            }
        };
        auto stA = [&](int st) {
            char* ah = sm + st * 16384;
            char* al = sm + st * 16384 + 8192;
#pragma unroll
            for (int i = 0; i < 4; i++) {
                int idx = tid + i * 256;
                int r = idx >> 4, c4 = idx & 15;
                uint32_t h0, l0, h1, l1;
                split2(apf[i].x, apf[i].y, h0, l0);
                split2(apf[i].z, apf[i].w, h1, l1);
                uint32_t so = r * 128 + ((uint32_t)((c4 >> 1) ^ (r & 7)) << 4) + (c4 & 1) * 8;
                *(uint2*)(ah + so) = make_uint2(h0, h1);
                *(uint2*)(al + so) = make_uint2(l0, l1);
            }
        };
        auto ldB = [&](int k0, int st) {
            uint32_t bh = sb + 32768 + st * 32768;
            uint32_t bl = bh + 16384;
#pragma unroll
            for (int i = 0; i < 4; i++) {
                int idx = tid + i * 256;
                int r = idx >> 3, c = idx & 7;
                uint32_t so = r * 128 + ((uint32_t)(c ^ (r & 7)) << 4);
                CP16(bh + so, &g_rwTh[(size_t)r * V_DIM + k0 + c * 8]);
                CP16(bl + so, &g_rwTl[(size_t)r * V_DIM + k0 + c * 8]);
            }
        };

        ldA(0);
        stA(0);
        ldB(0, 0); CP_COMMIT();
        ldA(64);

        for (int ch = 0; ch < 64; ch++) {
            const int s = ch & 1;
            cp_wait<0>();
            __syncthreads();
            if (ch < 63) { stA(1 - s); ldB((ch + 1) * 64, 1 - s); CP_COMMIT(); }
            if (ch < 62) ldA((ch + 2) * 64);

            const uint32_t ah0 = sb + s * 16384;
            const uint32_t al0 = ah0 + 8192;
            const uint32_t bh0 = sb + 32768 + s * 32768;
            const uint32_t bl0 = bh0 + 16384;
#pragma unroll
            for (int ks = 0; ks < 4; ks++) {
                uint32_t Ah[2][4], Al[2][4], Bh[4][2], Bl[4][2];
#pragma unroll
                for (int mf = 0; mf < 2; mf++) {
                    uint32_t rr = wr * 32 + mf * 16 + arow16;
                    uint32_t so = rr * 128 + ((uint32_t)((ks * 2 + ako) ^ (rr & 7)) << 4);
                    ldsm4(Ah[mf][0], Ah[mf][1], Ah[mf][2], Ah[mf][3], ah0 + so);
                    ldsm4(Al[mf][0], Al[mf][1], Al[mf][2], Al[mf][3], al0 + so);
                }
#pragma unroll
                for (int p = 0; p < 2; p++) {
                    uint32_t rr = wc * 32 + brow8 + p * 16;
                    uint32_t so = rr * 128 + ((uint32_t)((ks * 2 + bko) ^ (rr & 7)) << 4);
                    ldsm4(Bh[2 * p][0], Bh[2 * p][1], Bh[2 * p + 1][0], Bh[2 * p + 1][1], bh0 + so);
                    ldsm4(Bl[2 * p][0], Bl[2 * p][1], Bl[2 * p + 1][0], Bl[2 * p + 1][1], bl0 + so);
                }
#pragma unroll
                for (int mf = 0; mf < 2; mf++)
#pragma unroll
                    for (int nf = 0; nf < 4; nf++) {
                        mma_bf16(acc[mf][nf], Ah[mf], Bh[nf]);
                        mma_bf16(acc[mf][nf], Ah[mf], Bl[nf]);
                        mma_bf16(acc[mf][nf], Al[mf], Bh[nf]);
                    }
            }
        }
        __syncthreads();

        // prefetch W op0 kc0 into stage0 [0,32K) (A region, now free)
        {
            uint32_t wh = sb, wl = sb + 16384;
#pragma unroll
            for (int i = 0; i < 4; i++) {
                int idx = tid + i * 256;
                int r = idx >> 3, c = idx & 7;
                uint32_t so = r * 128 + ((uint32_t)(c ^ (r & 7)) << 4);
                CP16(wh + so, &g_wTh[r * C_DIM + c * 8]);
                CP16(wl + so, &g_wTl[r * C_DIM + c * 8]);
            }
            CP_COMMIT();
        }

        // vals -> smem (B-stage-1 region, reads done)
#pragma unroll
        for (int mf = 0; mf < 2; mf++)
#pragma unroll
            for (int nf = 0; nf < 4; nf++) {
                int r = wr * 32 + mf * 16 + (lane >> 2);
                int c = wc * 32 + nf * 8 + 2 * (lane & 3);
                uint32_t h0, l0, h1, l1;
                split2(acc[mf][nf][0], acc[mf][nf][1], h0, l0);
                split2(acc[mf][nf][2], acc[mf][nf][3], h1, l1);
                uint32_t so0 = r * 256 + ((uint32_t)((c >> 3) ^ (r & 7)) << 4) + ((c & 7) << 1);
                uint32_t so1 = (r + 8) * 256 + ((uint32_t)((c >> 3) ^ ((r + 8) & 7)) << 4) + ((c & 7) << 1);
                *(uint32_t*)(sm + VH + so0) = h0;
                *(uint32_t*)(sm + VL + so0) = l0;
                *(uint32_t*)(sm + VH + so1) = h1;
                *(uint32_t*)(sm + VL + so1) = l1;
            }
        __syncthreads();
    }

    // =========================== PHASE 2 ===========================
    // mix = sum_op wv[op] f_op(vals @ W_op + b); W streamed in 64-k chunks
    float res[2][4][4];
#pragma unroll
    for (int a = 0; a < 2; a++)
#pragma unroll
        for (int b = 0; b < 4; b++)
#pragma unroll
            for (int c = 0; c < 4; c++) res[a][b][c] = 0.0f;

    {
        float acc[2][4][4];
        auto ldW = [&](int op, int kc, int st) {
            uint32_t wh = sb + st * 32768;
            uint32_t wl = wh + 16384;
#pragma unroll
            for (int i = 0; i < 4; i++) {
                int idx = tid + i * 256;
                int r = idx >> 3, c = idx & 7;
                uint32_t so = r * 128 + ((uint32_t)(c ^ (r & 7)) << 4);
                CP16(wh + so, &g_wTh[(size_t)op * 16384 + r * C_DIM + kc * 64 + c * 8]);
                CP16(wl + so, &g_wTl[(size_t)op * 16384 + r * C_DIM + kc * 64 + c * 8]);
            }
        };
        auto ldP3 = [&](int n0, int st) {   // write_w 64-row n-tile, full K=128
            uint32_t bh = sb + st * 32768;
            uint32_t bl = bh + 16384;
#pragma unroll
            for (int i = 0; i < 4; i++) {
                int idx = tid + i * 256;
                int r = idx >> 4, c16 = idx & 15;
                uint32_t so = r * 256 + ((uint32_t)(c16 ^ (r & 7)) << 4);
                CP16(bh + so, &g_wwh[(size_t)(n0 + r) * C_DIM + c16 * 8]);
                CP16(bl + so, &g_wwl[(size_t)(n0 + r) * C_DIM + c16 * 8]);
            }
        };

#pragma unroll 1
        for (int it = 0; it < 16; it++) {
            const int op = it >> 1, kc = it & 1, st = it & 1;
            cp_wait<0>();
            __syncthreads();
            if (it < 15) { ldW((it + 1) >> 1, (it + 1) & 1, 1 - st); CP_COMMIT(); }
            else         { ldP3(0, 0); CP_COMMIT(); }

            if (kc == 0) {
#pragma unroll
                for (int a = 0; a < 2; a++)
#pragma unroll
                    for (int b = 0; b < 4; b++)
#pragma unroll
                        for (int c = 0; c < 4; c++) acc[a][b][c] = 0.0f;
            }

            const uint32_t wh0 = sb + st * 32768;
            const uint32_t wl0 = wh0 + 16384;
#pragma unroll
            for (int ks = 0; ks < 4; ks++) {
                uint32_t Ah[2][4], Al[2][4], Bh[4][2], Bl[4][2];
#pragma unroll
                for (int mf = 0; mf < 2; mf++) {
                    uint32_t rr = wr * 32 + mf * 16 + arow16;
                    uint32_t so = rr * 256 + ((uint32_t)((kc * 8 + ks * 2 + ako) ^ (rr & 7)) << 4);
                    ldsm4(Ah[mf][0], Ah[mf][1], Ah[mf][2], Ah[mf][3], sb + VH + so);
                    ldsm4(Al[mf][0], Al[mf][1], Al[mf][2], Al[mf][3], sb + VL + so);
                }
#pragma unroll
                for (int p = 0; p < 2; p++) {
                    uint32_t rr = wc * 32 + brow8 + p * 16;
                    uint32_t so = rr * 128 + ((uint32_t)((ks * 2 + bko) ^ (rr & 7)) << 4);
                    ldsm4(Bh[2 * p][0], Bh[2 * p][1], Bh[2 * p + 1][0], Bh[2 * p + 1][1], wh0 + so);
                    ldsm4(Bl[2 * p][0], Bl[2 * p][1], Bl[2 * p + 1][0], Bl[2 * p + 1][1], wl0 + so);
                }
#pragma unroll
                for (int mf = 0; mf < 2; mf++)
#pragma unroll
                    for (int nf = 0; nf < 4; nf++) {
                        mma_bf16(acc[mf][nf], Ah[mf], Bh[nf]);
                        mma_bf16(acc[mf][nf], Ah[mf], Bl[nf]);
                        mma_bf16(acc[mf][nf], Al[mf], Bh[nf]);
                    }
            }
            if (kc == 1) {
                const float w = wv[op];
#pragma unroll
                for (int mf = 0; mf < 2; mf++)
#pragma unroll
                    for (int nf = 0; nf < 4; nf++)
#pragma unroll
                        for (int j = 0; j < 4; j++) {
                            int col = wc * 32 + nf * 8 + 2 * (lane & 3) + (j & 1);
                            float v = acc[mf][nf][j] + bs[op * C_DIM + col];
                            float f;
                            switch (op) {
                                case 0: f = v; break;
                                case 1: f = fmaxf(v, 0.0f); break;
                                case 2: f = 0.5f * v * (1.0f + erff(v * 0.70710678118654752f)); break;
                                case 3: f = v * v; break;
                                case 4: f = -v; break;
                                case 5: f = fabsf(v); break;
                                case 6: f = tanhf(v); break;
                                default: f = 1.0f / (1.0f + expf(-v)); break;
                            }
                            res[mf][nf][j] += w * f;
                        }
            }
        }
    }

    // mix -> smem (overwrite vals after all reads)
    __syncthreads();
#pragma unroll
    for (int mf = 0; mf < 2; mf++)
#pragma unroll
        for (int nf = 0; nf < 4; nf++) {
            int r = wr * 32 + mf * 16 + (lane >> 2);
            int c = wc * 32 + nf * 8 + 2 * (lane & 3);
            uint32_t h0, l0, h1, l1;
            split2(res[mf][nf][0], res[mf][nf][1], h0, l0);
            split2(res[mf][nf][2], res[mf][nf][3], h1, l1);
            uint32_t so0 = r * 256 + ((uint32_t)((c >> 3) ^ (r & 7)) << 4) + ((c & 7) << 1);
            uint32_t so1 = (r + 8) * 256 + ((uint32_t)((c >> 3) ^ ((r + 8) & 7)) << 4) + ((c & 7) << 1);
            *(uint32_t*)(sm + VH + so0) = h0;
            *(uint32_t*)(sm + VL + so0) = l0;
            *(uint32_t*)(sm + VH + so1) = h1;
            *(uint32_t*)(sm + VL + so1) = l1;
        }
    __syncthreads();

    // =========================== PHASE 3 ===========================
    // out = mix @ write_w^T * alpha ; 64-col n-tiles, warp grid 4x2 (16x32)
    {
        const float alpha = __ldg(oscale);
        const int p3r = wid & 3, p3c = wid >> 2;
        auto ldP3 = [&](int n0, int st) {
            uint32_t bh = sb + st * 32768;
            uint32_t bl = bh + 16384;
#pragma unroll
            for (int i = 0; i < 4; i++) {
                int idx = tid + i * 256;
                int r = idx >> 4, c16 = idx & 15;
                uint32_t so = r * 256 + ((uint32_t)(c16 ^ (r & 7)) << 4);
                CP16(bh + so, &g_wwh[(size_t)(n0 + r) * C_DIM + c16 * 8]);
                CP16(bl + so, &g_wwl[(size_t)(n0 + r) * C_DIM + c16 * 8]);
            }
        };

#pragma unroll 1
        for (int nt = 0; nt < 64; nt++) {
            const int st = nt & 1;
            cp_wait<0>();
            __syncthreads();
            if (nt < 63) { ldP3((nt + 1) * 64, 1 - st); CP_COMMIT(); }

            float acc[4][4];
#pragma unroll
            for (int b = 0; b < 4; b++)
#pragma unroll
                for (int c = 0; c < 4; c++) acc[b][c] = 0.0f;

            const uint32_t bh0 = sb + st * 32768;
            const uint32_t bl0 = bh0 + 16384;
#pragma unroll
            for (int ks = 0; ks < 8; ks++) {
                uint32_t Ah[4], Al[4], Bh[4][2], Bl[4][2];
                {
                    uint32_t rr = p3r * 16 + arow16;
                    uint32_t so = rr * 256 + ((uint32_t)((ks * 2 + ako) ^ (rr & 7)) << 4);
                    ldsm4(Ah[0], Ah[1], Ah[2], Ah[3], sb + VH + so);
                    ldsm4(Al[0], Al[1], Al[2], Al[3], sb + VL + so);
                }
#pragma unroll
                for (int p = 0; p < 2; p++) {
                    uint32_t rr = p3c * 32 + brow8 + p * 16;
                    uint32_t so = rr * 256 + ((uint32_t)((ks * 2 + bko) ^ (rr & 7)) << 4);
                    ldsm4(Bh[2 * p][0], Bh[2 * p][1], Bh[2 * p + 1][0], Bh[2 * p + 1][1], bh0 + so);
                    ldsm4(Bl[2 * p][0], Bl[2 * p][1], Bl[2 * p + 1][0], Bl[2 * p + 1][1], bl0 + so);
                }
#pragma unroll
                for (int nf = 0; nf < 4; nf++) {
                    mma_bf16(acc[nf], Ah, Bh[nf]);
                    mma_bf16(acc[nf], Ah, Bl[nf]);
                    mma_bf16(acc[nf], Al, Bh[nf]);
                }
            }
#pragma unroll
            for (int nf = 0; nf < 4; nf++) {
                int r = m0 + p3r * 16 + (lane >> 2);
                int c = nt * 64 + p3c * 32 + nf * 8 + 2 * (lane & 3);
                float2 v0 = make_float2(acc[nf][0] * alpha, acc[nf][1] * alpha);
                float2 v1 = make_float2(acc[nf][2] * alpha, acc[nf][3] * alpha);
                *(float2*)&out[(size_t)r * V_DIM + c] = v0;
                *(float2*)&out[(size_t)(r + 8) * V_DIM + c] = v1;
            }
        }
    }
}

// ---------------------------------------------------------------------------
extern "C" void kernel_launch(void* const* d_in, const int* in_sizes, int n_in,
                              void* d_out, int out_size)
{
    const float* x      = (const float*)d_in[0];
    const float* basis  = (const float*)d_in[1];
    const float* rcoef  = (const float*)d_in[2];
    const float* wcoef  = (const float*)d_in[3];
    const float* logits = (const float*)d_in[4];
    const float* opW    = (const float*)d_in[5];
    const float* opB    = (const float*)d_in[6];
    const float* oscale = (const float*)d_in[7];
    float* out = (float*)d_out;

    float* p_rw;
    cudaGetSymbolAddress((void**)&p_rw, g_rw);

    static bool attr_done = false;
    if (!attr_done) {
        cudaFuncSetAttribute(mega, cudaFuncAttributeMaxDynamicSharedMemorySize, 98304);
        attr_done = true;
    }

    sgemm_addr<<<dim3(1, V_DIM / 128, 2), 256>>>(basis, rcoef, wcoef);
    col_softmax_T<<<C_DIM, 256>>>(p_rw);
    prep_wT<<<N_OPS * C_DIM * C_DIM / 256, 256>>>(opW);
    mega<<<M_TOK / MT, 256, 98304>>>(x, logits, opB, out, oscale);
}